// round 1
// baseline (speedup 1.0000x reference)
#include <cuda_runtime.h>
#include <cuda_bf16.h>
#include <math.h>

#define N_NODES 50000
#define N_EDGES 800000
#define IN_F    256
#define OUT_F   64
#define N_HEADS 8
#define HF      (N_HEADS * OUT_F)   // 512

// ---------------- device scratch (static: allocated at module load, allowed) ----
__device__ float g_h[(size_t)N_NODES * HF];        // [N, H, 64] transformed features (~102 MB)
__device__ float g_aself[N_NODES * N_HEADS];
__device__ float g_aneigh[N_NODES * N_HEADS];
__device__ int   g_deg[N_NODES];
__device__ int   g_offs[N_NODES + 1];
__device__ int   g_cursor[N_NODES];
__device__ int   g_csr_src[N_EDGES];
__device__ float g_csr_m[N_EDGES];

// ---------------- CSR build --------------------------------------------------
__global__ void k_zero_deg() {
    int i = blockIdx.x * blockDim.x + threadIdx.x;
    if (i < N_NODES) g_deg[i] = 0;
}

__global__ void k_count(const int* __restrict__ dst) {
    int e = blockIdx.x * blockDim.x + threadIdx.x;
    if (e < N_EDGES) atomicAdd(&g_deg[dst[e]], 1);
}

// single-block exclusive scan over degrees -> offsets + cursor copy
__global__ void k_scan() {
    __shared__ int sm[1024];
    int tid = threadIdx.x;
    int carry = 0;
    for (int base = 0; base < N_NODES; base += 1024) {
        int i = base + tid;
        int v = (i < N_NODES) ? g_deg[i] : 0;
        sm[tid] = v;
        __syncthreads();
        for (int off = 1; off < 1024; off <<= 1) {
            int t = (tid >= off) ? sm[tid - off] : 0;
            __syncthreads();
            sm[tid] += t;
            __syncthreads();
        }
        if (i < N_NODES) {
            int excl = carry + sm[tid] - v;
            g_offs[i]   = excl;
            g_cursor[i] = excl;
        }
        carry += sm[1023];
        __syncthreads();
    }
    if (tid == 0) g_offs[N_NODES] = carry;
}

__global__ void k_fill(const int* __restrict__ src, const int* __restrict__ dst,
                       const float* __restrict__ M) {
    int e = blockIdx.x * blockDim.x + threadIdx.x;
    if (e < N_EDGES) {
        int d = dst[e];
        int p = atomicAdd(&g_cursor[d], 1);
        g_csr_src[p] = src[e];
        g_csr_m[p]   = M[e];
    }
}

// ---------------- GEMM: h[n, hd*64+f] = sum_k x[n,k] * W[hd,k,f] -------------
// BM=128, BN=64 (one full head), BK=32, 256 threads, 8x4 micro-tile.
__global__ void __launch_bounds__(256, 2) k_gemm(const float* __restrict__ x,
                                                 const float* __restrict__ W) {
    __shared__ float As[32][132];   // [k][row], padded
    __shared__ float Bs[32][64];    // [k][col]

    const int tid = threadIdx.x;
    const int tx = tid & 15;        // col group  (x4)
    const int ty = tid >> 4;        // row group  (x8)
    const int row0 = blockIdx.x * 128;
    const int hd = blockIdx.y;
    const float* Wh = W + (size_t)hd * IN_F * OUT_F;

    float acc[8][4];
#pragma unroll
    for (int i = 0; i < 8; i++)
#pragma unroll
        for (int j = 0; j < 4; j++) acc[i][j] = 0.f;

    for (int k0 = 0; k0 < IN_F; k0 += 32) {
        // load x tile [128 rows x 32 k] transposed into As
#pragma unroll
        for (int t = 0; t < 4; t++) {
            int li = tid + t * 256;          // 0..1023
            int r  = li >> 3;                // 0..127
            int k4 = (li & 7) << 2;          // 0,4,...,28
            int grow = row0 + r;
            float4 v = make_float4(0.f, 0.f, 0.f, 0.f);
            if (grow < N_NODES)
                v = *(const float4*)(x + (size_t)grow * IN_F + k0 + k4);
            As[k4 + 0][r] = v.x;
            As[k4 + 1][r] = v.y;
            As[k4 + 2][r] = v.z;
            As[k4 + 3][r] = v.w;
        }
        // load W tile [32 k x 64 cols]
#pragma unroll
        for (int t = 0; t < 2; t++) {
            int li = tid + t * 256;          // 0..511
            int kk = li >> 4;                // 0..31
            int n4 = (li & 15) << 2;         // 0..60
            *(float4*)&Bs[kk][n4] =
                *(const float4*)(Wh + (size_t)(k0 + kk) * OUT_F + n4);
        }
        __syncthreads();

#pragma unroll
        for (int kk = 0; kk < 32; kk++) {
            float4 a0 = *(const float4*)&As[kk][ty * 8];
            float4 a1 = *(const float4*)&As[kk][ty * 8 + 4];
            float4 b  = *(const float4*)&Bs[kk][tx * 4];
            float ra[8] = {a0.x, a0.y, a0.z, a0.w, a1.x, a1.y, a1.z, a1.w};
            float rb[4] = {b.x, b.y, b.z, b.w};
#pragma unroll
            for (int i = 0; i < 8; i++)
#pragma unroll
                for (int j = 0; j < 4; j++)
                    acc[i][j] = fmaf(ra[i], rb[j], acc[i][j]);
        }
        __syncthreads();
    }

#pragma unroll
    for (int i = 0; i < 8; i++) {
        int grow = row0 + ty * 8 + i;
        if (grow < N_NODES) {
            float4 v = make_float4(acc[i][0], acc[i][1], acc[i][2], acc[i][3]);
            *(float4*)(g_h + (size_t)grow * HF + hd * OUT_F + tx * 4) = v;
        }
    }
}

// ---------------- attention logit dots: warp per (node, head) ----------------
__global__ void k_adot(const float* __restrict__ a) {
    int wid = threadIdx.x >> 5, lane = threadIdx.x & 31;
    int gid = blockIdx.x * 8 + wid;
    if (gid >= N_NODES * N_HEADS) return;
    int n = gid >> 3, hd = gid & 7;
    const float* hp = g_h + (size_t)n * HF + hd * OUT_F;
    float v0 = hp[lane], v1 = hp[lane + 32];
    const float* a0 = a + hd * 2 * OUT_F;        // a[hd,0,:]
    const float* a1 = a0 + OUT_F;                // a[hd,1,:]
    float s0 = v0 * a0[lane] + v1 * a0[lane + 32];
    float s1 = v0 * a1[lane] + v1 * a1[lane + 32];
#pragma unroll
    for (int o = 16; o; o >>= 1) {
        s0 += __shfl_xor_sync(0xffffffffu, s0, o);
        s1 += __shfl_xor_sync(0xffffffffu, s1, o);
    }
    if (lane == 0) {
        g_aself[n * N_HEADS + hd]  = s0;
        g_aneigh[n * N_HEADS + hd] = s1;
    }
}

// ---------------- fused softmax + aggregation: warp per (dst, head) ----------
// head-major pair ordering so concurrent warps share one 12.8 MB head slice of h (L2-resident)
__global__ void k_agg(float* __restrict__ out) {
    int wid = threadIdx.x >> 5, lane = threadIdx.x & 31;
    int pair = blockIdx.x * 8 + wid;
    if (pair >= N_NODES * N_HEADS) return;
    int hd = pair / N_NODES;
    int n  = pair - hd * N_NODES;

    float an = g_aneigh[n * N_HEADS + hd];
    int s = g_offs[n], e = g_offs[n + 1];
    float acc0 = 0.f, acc1 = 0.f, den = 0.f;
    const int bh = hd * OUT_F;

    for (int i = s; i < e; i++) {
        int   u = g_csr_src[i];
        float m = g_csr_m[i];
        float ev = g_aself[u * N_HEADS + hd] + an;
        ev = (ev > 0.f) ? ev : 0.2f * ev;       // leaky_relu, slope 0.2
        float w = __expf(ev * m);               // exp(leaky(...) * M)
        const float* hp = g_h + (size_t)u * HF + bh;
        acc0 = fmaf(w, hp[lane],      acc0);
        acc1 = fmaf(w, hp[lane + 32], acc1);
        den += w;
    }
    float inv = 1.f / (den + 1e-16f);
    float o0 = acc0 * inv, o1 = acc1 * inv;
    o0 = (o0 > 0.f) ? o0 : expm1f(o0);          // elu
    o1 = (o1 > 0.f) ? o1 : expm1f(o1);
    out[(size_t)n * HF + bh + lane]      = o0;
    out[(size_t)n * HF + bh + 32 + lane] = o1;
}

// ---------------- launch -----------------------------------------------------
extern "C" void kernel_launch(void* const* d_in, const int* in_sizes, int n_in,
                              void* d_out, int out_size) {
    const float* x   = (const float*)d_in[0];
    const int*   src = (const int*)d_in[1];
    const int*   dst = (const int*)d_in[2];
    const float* M   = (const float*)d_in[3];
    const float* W   = (const float*)d_in[4];
    const float* a   = (const float*)d_in[5];
    float* out = (float*)d_out;

    k_zero_deg<<<(N_NODES + 255) / 256, 256>>>();
    k_count<<<(N_EDGES + 255) / 256, 256>>>(dst);
    k_scan<<<1, 1024>>>();
    k_fill<<<(N_EDGES + 255) / 256, 256>>>(src, dst, M);
    k_gemm<<<dim3((N_NODES + 127) / 128, N_HEADS), 256>>>(x, W);
    k_adot<<<N_NODES, 256>>>(a);
    k_agg<<<N_NODES, 256>>>(out);
}

// round 3
// speedup vs baseline: 1.2451x; 1.2451x over previous
#include <cuda_runtime.h>
#include <cuda_bf16.h>
#include <stdint.h>
#include <math.h>

#define N_NODES 50000
#define N_EDGES 800000
#define IN_F    256
#define OUT_F   64
#define N_HEADS 8
#define HF      (N_HEADS * OUT_F)   // 512

// ---------------- device scratch ---------------------------------------------
__device__ float g_h[(size_t)N_NODES * HF];        // [N, H, 64] fp32 (~102 MB)
__device__ float g_aself[N_NODES * N_HEADS];
__device__ float g_aneigh[N_NODES * N_HEADS];
__device__ int   g_deg[N_NODES];
__device__ int   g_offs[N_NODES + 1];
__device__ int   g_cursor[N_NODES];
__device__ int   g_csr_src[N_EDGES];
__device__ float g_csr_m[N_EDGES];
// bf16x3 split operands
__device__ __nv_bfloat16 g_xhi[(size_t)N_NODES * IN_F];
__device__ __nv_bfloat16 g_xlo[(size_t)N_NODES * IN_F];
__device__ __nv_bfloat16 g_wthi[N_HEADS * OUT_F * IN_F];   // [hd][n][k]
__device__ __nv_bfloat16 g_wtlo[N_HEADS * OUT_F * IN_F];

// ---------------- operand prep (fp32 -> bf16 hi/lo split) --------------------
__global__ void k_prep_x(const float* __restrict__ x) {
    int i = blockIdx.x * blockDim.x + threadIdx.x;          // pair index
    const int total = N_NODES * IN_F / 2;
    if (i < total) {
        float2 v = ((const float2*)x)[i];
        __nv_bfloat16 h0 = __float2bfloat16_rn(v.x);
        __nv_bfloat16 h1 = __float2bfloat16_rn(v.y);
        __nv_bfloat16 l0 = __float2bfloat16_rn(v.x - __bfloat162float(h0));
        __nv_bfloat16 l1 = __float2bfloat16_rn(v.y - __bfloat162float(h1));
        ((__nv_bfloat162*)g_xhi)[i] = __halves2bfloat162(h0, h1);
        ((__nv_bfloat162*)g_xlo)[i] = __halves2bfloat162(l0, l1);
    }
}

// W [hd][k][n] fp32  ->  Wt [hd][n][k] bf16 hi/lo
__global__ void k_prep_w(const float* __restrict__ W) {
    int i = blockIdx.x * blockDim.x + threadIdx.x;          // [hd][n][k] linear
    if (i < N_HEADS * OUT_F * IN_F) {
        int k  = i & (IN_F - 1);
        int n  = (i >> 8) & (OUT_F - 1);
        int hd = i >> 14;
        float v = W[((size_t)hd * IN_F + k) * OUT_F + n];
        __nv_bfloat16 hi = __float2bfloat16_rn(v);
        __nv_bfloat16 lo = __float2bfloat16_rn(v - __bfloat162float(hi));
        g_wthi[i] = hi;
        g_wtlo[i] = lo;
    }
}

// ---------------- CSR build --------------------------------------------------
__global__ void k_zero_deg() {
    int i = blockIdx.x * blockDim.x + threadIdx.x;
    if (i < N_NODES) g_deg[i] = 0;
}

__global__ void k_count(const int* __restrict__ dst) {
    int e = blockIdx.x * blockDim.x + threadIdx.x;
    if (e < N_EDGES) atomicAdd(&g_deg[dst[e]], 1);
}

__global__ void k_scan() {
    __shared__ int sm[1024];
    int tid = threadIdx.x;
    int carry = 0;
    for (int base = 0; base < N_NODES; base += 1024) {
        int i = base + tid;
        int v = (i < N_NODES) ? g_deg[i] : 0;
        sm[tid] = v;
        __syncthreads();
        for (int off = 1; off < 1024; off <<= 1) {
            int t = (tid >= off) ? sm[tid - off] : 0;
            __syncthreads();
            sm[tid] += t;
            __syncthreads();
        }
        if (i < N_NODES) {
            int excl = carry + sm[tid] - v;
            g_offs[i]   = excl;
            g_cursor[i] = excl;
        }
        carry += sm[1023];
        __syncthreads();
    }
    if (tid == 0) g_offs[N_NODES] = carry;
}

__global__ void k_fill(const int* __restrict__ src, const int* __restrict__ dst,
                       const float* __restrict__ M) {
    int e = blockIdx.x * blockDim.x + threadIdx.x;
    if (e < N_EDGES) {
        int d = dst[e];
        int p = atomicAdd(&g_cursor[d], 1);
        g_csr_src[p] = src[e];
        g_csr_m[p]   = M[e];
    }
}

// ---------------- bf16x3 tensor-core GEMM + fused attention dots -------------
// Block = 128 rows x 64 cols (one head). 8 warps, each warp: m16 x n64.
// mma.sync.m16n8k16 bf16->fp32;  acc += hi*hi + hi*lo + lo*hi.
#define MMA_BF16(d, a0, a1, a2, a3, b0, b1)                                   \
    asm volatile(                                                             \
        "mma.sync.aligned.m16n8k16.row.col.f32.bf16.bf16.f32 "                \
        "{%0,%1,%2,%3}, {%4,%5,%6,%7}, {%8,%9}, {%0,%1,%2,%3};"               \
        : "+f"(d[0]), "+f"(d[1]), "+f"(d[2]), "+f"(d[3])                      \
        : "r"(a0), "r"(a1), "r"(a2), "r"(a3), "r"(b0), "r"(b1))

__global__ void __launch_bounds__(256, 2) k_gemm(const float* __restrict__ a_vec) {
    // row stride 20 words (80B): 16B-aligned for uint4 stores, and
    // (20*g + tig) mod 32 covers all 32 banks -> conflict-free fragment loads
    __shared__ uint32_t As_h[128][20], As_l[128][20];
    __shared__ uint32_t Bs_h[64][20],  Bs_l[64][20];

    const int tid  = threadIdx.x;
    const int w    = tid >> 5;
    const int lane = tid & 31;
    const int g    = lane >> 2;      // group 0..7
    const int tig  = lane & 3;       // thread-in-group
    const int row0 = blockIdx.x * 128;
    const int hd   = blockIdx.y;

    float acc[8][4];
#pragma unroll
    for (int j = 0; j < 8; j++)
#pragma unroll
        for (int i = 0; i < 4; i++) acc[j][i] = 0.f;

    const uint4* xh4 = (const uint4*)g_xhi;   // 32 uint4 per row (256 bf16)
    const uint4* xl4 = (const uint4*)g_xlo;
    const uint4* wh4 = (const uint4*)g_wthi;
    const uint4* wl4 = (const uint4*)g_wtlo;

    for (int k0 = 0; k0 < 32; k0 += 4) {     // k0 in uint4 units (BK=32 bf16)
        // ---- stage tiles ----
#pragma unroll
        for (int t = 0; t < 2; t++) {
            int li = tid + t * 256;
            int r = li >> 2, q = li & 3;
            int grow = row0 + r;
            uint4 vh = make_uint4(0u, 0u, 0u, 0u), vl = vh;
            if (grow < N_NODES) {
                vh = xh4[(size_t)grow * 32 + k0 + q];
                vl = xl4[(size_t)grow * 32 + k0 + q];
            }
            *(uint4*)&As_h[r][q * 4] = vh;
            *(uint4*)&As_l[r][q * 4] = vl;
        }
        {
            int r = tid >> 2, q = tid & 3;
            *(uint4*)&Bs_h[r][q * 4] = wh4[(hd * 64 + r) * 32 + k0 + q];
            *(uint4*)&Bs_l[r][q * 4] = wl4[(hd * 64 + r) * 32 + k0 + q];
        }
        __syncthreads();

        // ---- compute: 2 k16 steps ----
#pragma unroll
        for (int kt = 0; kt < 2; kt++) {
            const int kw = kt * 8;
            const int ra = w * 16 + g;
            uint32_t ah0 = As_h[ra][kw + tig],     ah1 = As_h[ra + 8][kw + tig];
            uint32_t ah2 = As_h[ra][kw + tig + 4], ah3 = As_h[ra + 8][kw + tig + 4];
            uint32_t al0 = As_l[ra][kw + tig],     al1 = As_l[ra + 8][kw + tig];
            uint32_t al2 = As_l[ra][kw + tig + 4], al3 = As_l[ra + 8][kw + tig + 4];
#pragma unroll
            for (int j = 0; j < 8; j++) {
                const int rb = j * 8 + g;
                uint32_t bh0 = Bs_h[rb][kw + tig], bh1 = Bs_h[rb][kw + tig + 4];
                uint32_t bl0 = Bs_l[rb][kw + tig], bl1 = Bs_l[rb][kw + tig + 4];
                MMA_BF16(acc[j], ah0, ah1, ah2, ah3, bh0, bh1);
                MMA_BF16(acc[j], ah0, ah1, ah2, ah3, bl0, bl1);
                MMA_BF16(acc[j], al0, al1, al2, al3, bh0, bh1);
            }
        }
        __syncthreads();
    }

    // ---- epilogue: fused attention dots + h store ----
    // thread holds: rows (ra, ra+8), cols j*8 + 2*tig (+1), j = 0..7
    const int ra = row0 + w * 16 + g;
    const float* ac = a_vec + hd * 2 * OUT_F;     // a[hd,0,:] then a[hd,1,:]
    float s0 = 0.f, s1 = 0.f, t0 = 0.f, t1 = 0.f;
#pragma unroll
    for (int j = 0; j < 8; j++) {
        int c = j * 8 + 2 * tig;
        float2 as = *(const float2*)(ac + c);
        float2 an = *(const float2*)(ac + OUT_F + c);
        s0 += acc[j][0] * as.x + acc[j][1] * as.y;
        s1 += acc[j][2] * as.x + acc[j][3] * as.y;
        t0 += acc[j][0] * an.x + acc[j][1] * an.y;
        t1 += acc[j][2] * an.x + acc[j][3] * an.y;
    }
#pragma unroll
    for (int o = 1; o < 4; o <<= 1) {            // reduce within quad
        s0 += __shfl_xor_sync(0xffffffffu, s0, o);
        s1 += __shfl_xor_sync(0xffffffffu, s1, o);
        t0 += __shfl_xor_sync(0xffffffffu, t0, o);
        t1 += __shfl_xor_sync(0xffffffffu, t1, o);
    }
    if (tig == 0) {
        if (ra < N_NODES) {
            g_aself[ra * N_HEADS + hd]  = s0;
            g_aneigh[ra * N_HEADS + hd] = t0;
        }
        if (ra + 8 < N_NODES) {
            g_aself[(ra + 8) * N_HEADS + hd]  = s1;
            g_aneigh[(ra + 8) * N_HEADS + hd] = t1;
        }
    }
    if (ra < N_NODES) {
        float* hp = g_h + (size_t)ra * HF + hd * OUT_F;
#pragma unroll
        for (int j = 0; j < 8; j++)
            *(float2*)(hp + j * 8 + 2 * tig) = make_float2(acc[j][0], acc[j][1]);
    }
    if (ra + 8 < N_NODES) {
        float* hp = g_h + (size_t)(ra + 8) * HF + hd * OUT_F;
#pragma unroll
        for (int j = 0; j < 8; j++)
            *(float2*)(hp + j * 8 + 2 * tig) = make_float2(acc[j][2], acc[j][3]);
    }
}

// ---------------- fused softmax + aggregation: warp per (dst, head) ----------
__global__ void k_agg(float* __restrict__ out) {
    int wid = threadIdx.x >> 5, lane = threadIdx.x & 31;
    int pair = blockIdx.x * 8 + wid;
    if (pair >= N_NODES * N_HEADS) return;
    int hd = pair / N_NODES;
    int n  = pair - hd * N_NODES;

    float an = g_aneigh[n * N_HEADS + hd];
    int s = g_offs[n], e = g_offs[n + 1];
    float acc0 = 0.f, acc1 = 0.f, den = 0.f;
    const int bh = hd * OUT_F;

    for (int i = s; i < e; i++) {
        int   u = g_csr_src[i];
        float m = g_csr_m[i];
        float ev = g_aself[u * N_HEADS + hd] + an;
        ev = (ev > 0.f) ? ev : 0.2f * ev;       // leaky_relu, slope 0.2
        float wgt = __expf(ev * m);
        const float* hp = g_h + (size_t)u * HF + bh;
        acc0 = fmaf(wgt, hp[lane],      acc0);
        acc1 = fmaf(wgt, hp[lane + 32], acc1);
        den += wgt;
    }
    float inv = 1.f / (den + 1e-16f);
    float o0 = acc0 * inv, o1 = acc1 * inv;
    o0 = (o0 > 0.f) ? o0 : expm1f(o0);          // elu
    o1 = (o1 > 0.f) ? o1 : expm1f(o1);
    out[(size_t)n * HF + bh + lane]      = o0;
    out[(size_t)n * HF + bh + 32 + lane] = o1;
}

// ---------------- launch -----------------------------------------------------
extern "C" void kernel_launch(void* const* d_in, const int* in_sizes, int n_in,
                              void* d_out, int out_size) {
    const float* x   = (const float*)d_in[0];
    const int*   src = (const int*)d_in[1];
    const int*   dst = (const int*)d_in[2];
    const float* M   = (const float*)d_in[3];
    const float* W   = (const float*)d_in[4];
    const float* a   = (const float*)d_in[5];
    float* out = (float*)d_out;

    // order chosen so launch slot 5 (ncu -s 5 -c 1) is k_gemm
    k_prep_x<<<(N_NODES * IN_F / 2 + 255) / 256, 256>>>(x);             // 0
    k_prep_w<<<(N_HEADS * OUT_F * IN_F + 255) / 256, 256>>>(W);         // 1
    k_zero_deg<<<(N_NODES + 255) / 256, 256>>>();                       // 2
    k_count<<<(N_EDGES + 255) / 256, 256>>>(dst);                       // 3
    k_scan<<<1, 1024>>>();                                              // 4
    k_gemm<<<dim3((N_NODES + 127) / 128, N_HEADS), 256>>>(a);           // 5
    k_fill<<<(N_EDGES + 255) / 256, 256>>>(src, dst, M);                // 6
    k_agg<<<N_NODES, 256>>>(out);                                       // 7
}

// round 4
// speedup vs baseline: 1.5179x; 1.2191x over previous
#include <cuda_runtime.h>
#include <cuda_bf16.h>
#include <cuda_fp16.h>
#include <stdint.h>
#include <math.h>

#define N_NODES 50000
#define N_EDGES 800000
#define IN_F    256
#define OUT_F   64
#define N_HEADS 8
#define HF      (N_HEADS * OUT_F)   // 512

// ---------------- device scratch ---------------------------------------------
__device__ __half g_hh[(size_t)N_NODES * HF];      // fp16 h for gather (~51 MB)
__device__ float g_aself[N_NODES * N_HEADS];
__device__ float g_aneigh[N_NODES * N_HEADS];
__device__ int   g_deg[N_NODES];
__device__ int   g_offs[N_NODES + 1];
__device__ int   g_cursor[N_NODES];
__device__ int   g_csr_src[N_EDGES];
__device__ float g_csr_w[(size_t)N_EDGES * N_HEADS];   // per-edge per-head exp weights
// bf16x3 split operands
__device__ __nv_bfloat16 g_xhi[(size_t)N_NODES * IN_F];
__device__ __nv_bfloat16 g_xlo[(size_t)N_NODES * IN_F];
__device__ __nv_bfloat16 g_wthi[N_HEADS * OUT_F * IN_F];   // [hd][n][k]
__device__ __nv_bfloat16 g_wtlo[N_HEADS * OUT_F * IN_F];

// ---------------- operand prep (fp32 -> bf16 hi/lo split) --------------------
__global__ void k_prep_x(const float* __restrict__ x) {
    int i = blockIdx.x * blockDim.x + threadIdx.x;
    const int total = N_NODES * IN_F / 2;
    if (i < total) {
        float2 v = ((const float2*)x)[i];
        __nv_bfloat16 h0 = __float2bfloat16_rn(v.x);
        __nv_bfloat16 h1 = __float2bfloat16_rn(v.y);
        __nv_bfloat16 l0 = __float2bfloat16_rn(v.x - __bfloat162float(h0));
        __nv_bfloat16 l1 = __float2bfloat16_rn(v.y - __bfloat162float(h1));
        ((__nv_bfloat162*)g_xhi)[i] = __halves2bfloat162(h0, h1);
        ((__nv_bfloat162*)g_xlo)[i] = __halves2bfloat162(l0, l1);
    }
}

__global__ void k_prep_w(const float* __restrict__ W) {
    int i = blockIdx.x * blockDim.x + threadIdx.x;          // [hd][n][k] linear
    if (i < N_HEADS * OUT_F * IN_F) {
        int k  = i & (IN_F - 1);
        int n  = (i >> 8) & (OUT_F - 1);
        int hd = i >> 14;
        float v = W[((size_t)hd * IN_F + k) * OUT_F + n];
        __nv_bfloat16 hi = __float2bfloat16_rn(v);
        __nv_bfloat16 lo = __float2bfloat16_rn(v - __bfloat162float(hi));
        g_wthi[i] = hi;
        g_wtlo[i] = lo;
    }
}

// ---------------- CSR build --------------------------------------------------
__global__ void k_zero_deg() {
    int i = blockIdx.x * blockDim.x + threadIdx.x;
    if (i < N_NODES) g_deg[i] = 0;
}

__global__ void k_count(const int* __restrict__ dst) {
    int e = blockIdx.x * blockDim.x + threadIdx.x;
    if (e < N_EDGES) atomicAdd(&g_deg[dst[e]], 1);
}

// 1024-thread block scan, shuffle-based
__global__ void k_scan() {
    __shared__ int warp_sums[32];
    int tid = threadIdx.x, lane = tid & 31, wid = tid >> 5;
    int carry = 0;
    for (int base = 0; base < N_NODES; base += 1024) {
        int i = base + tid;
        int v = (i < N_NODES) ? g_deg[i] : 0;
        int xsum = v;
#pragma unroll
        for (int o = 1; o < 32; o <<= 1) {
            int t = __shfl_up_sync(0xffffffffu, xsum, o);
            if (lane >= o) xsum += t;
        }
        if (lane == 31) warp_sums[wid] = xsum;
        __syncthreads();
        if (wid == 0) {
            int s = warp_sums[lane];
#pragma unroll
            for (int o = 1; o < 32; o <<= 1) {
                int t = __shfl_up_sync(0xffffffffu, s, o);
                if (lane >= o) s += t;
            }
            warp_sums[lane] = s;
        }
        __syncthreads();
        int woff = (wid == 0) ? 0 : warp_sums[wid - 1];
        int incl = xsum + woff;
        if (i < N_NODES) {
            int excl = carry + incl - v;
            g_offs[i]   = excl;
            g_cursor[i] = excl;
        }
        carry += warp_sums[31];
        __syncthreads();
    }
    if (tid == 0) g_offs[N_NODES] = carry;
}

// fill CSR + fused per-edge-head softmax numerators (needs aself/aneigh: after gemm)
__global__ void k_fill(const int* __restrict__ src, const int* __restrict__ dst,
                       const float* __restrict__ M) {
    int e = blockIdx.x * blockDim.x + threadIdx.x;
    if (e >= N_EDGES) return;
    int s = src[e], d = dst[e];
    float m = M[e];
    int p = atomicAdd(&g_cursor[d], 1);
    g_csr_src[p] = s;
    float4 as0 = *(const float4*)&g_aself[s * 8];
    float4 as1 = *(const float4*)&g_aself[s * 8 + 4];
    float4 an0 = *(const float4*)&g_aneigh[d * 8];
    float4 an1 = *(const float4*)&g_aneigh[d * 8 + 4];
    float ev[8] = {as0.x + an0.x, as0.y + an0.y, as0.z + an0.z, as0.w + an0.w,
                   as1.x + an1.x, as1.y + an1.y, as1.z + an1.z, as1.w + an1.w};
    float wv[8];
#pragma unroll
    for (int hd = 0; hd < 8; hd++) {
        float t = ev[hd];
        t = (t > 0.f) ? t : 0.2f * t;          // leaky_relu
        wv[hd] = __expf(t * m);
    }
    float4* wp = (float4*)&g_csr_w[(size_t)p * 8];
    wp[0] = make_float4(wv[0], wv[1], wv[2], wv[3]);
    wp[1] = make_float4(wv[4], wv[5], wv[6], wv[7]);
}

// ---------------- bf16x3 tensor-core GEMM + fused attention dots -------------
#define MMA_BF16(d, a0, a1, a2, a3, b0, b1)                                   \
    asm volatile(                                                             \
        "mma.sync.aligned.m16n8k16.row.col.f32.bf16.bf16.f32 "                \
        "{%0,%1,%2,%3}, {%4,%5,%6,%7}, {%8,%9}, {%0,%1,%2,%3};"               \
        : "+f"(d[0]), "+f"(d[1]), "+f"(d[2]), "+f"(d[3])                      \
        : "r"(a0), "r"(a1), "r"(a2), "r"(a3), "r"(b0), "r"(b1))

#define LDSM_X4(r, addr)                                                      \
    asm volatile("ldmatrix.sync.aligned.m8n8.x4.shared.b16 {%0,%1,%2,%3}, [%4];" \
        : "=r"((r)[0]), "=r"((r)[1]), "=r"((r)[2]), "=r"((r)[3]) : "r"(addr))

__global__ void __launch_bounds__(256, 2) k_gemm(const float* __restrict__ a_vec) {
    // row stride 20 words (80B): 16B-aligned, conflict-free
    __shared__ uint32_t As_h[128][20], As_l[128][20];
    __shared__ uint32_t Bs_h[64][20],  Bs_l[64][20];

    const int tid  = threadIdx.x;
    const int w    = tid >> 5;
    const int lane = tid & 31;
    const int g    = lane >> 2;
    const int tig  = lane & 3;
    const int row0 = blockIdx.x * 128;
    const int hd   = blockIdx.y;

    float acc[8][4];
#pragma unroll
    for (int j = 0; j < 8; j++)
#pragma unroll
        for (int i = 0; i < 4; i++) acc[j][i] = 0.f;

    // ldmatrix per-lane base addresses
    const int a_row  = w * 16 + (lane & 15);
    const int a_colw = (lane >> 4) * 4;
    uint32_t aaddr_h = (uint32_t)__cvta_generic_to_shared(&As_h[a_row][a_colw]);
    uint32_t aaddr_l = (uint32_t)__cvta_generic_to_shared(&As_l[a_row][a_colw]);
    const int b_row  = (lane & 7) + ((lane >> 4) << 3);     // + q*16 later
    const int b_colw = ((lane >> 3) & 1) * 4;
    uint32_t baddr_h = (uint32_t)__cvta_generic_to_shared(&Bs_h[b_row][b_colw]);
    uint32_t baddr_l = (uint32_t)__cvta_generic_to_shared(&Bs_l[b_row][b_colw]);

    const uint4* xh4 = (const uint4*)g_xhi;
    const uint4* xl4 = (const uint4*)g_xlo;
    const uint4* wh4 = (const uint4*)g_wthi;
    const uint4* wl4 = (const uint4*)g_wtlo;

    for (int k0 = 0; k0 < 32; k0 += 4) {     // uint4 units (BK=32 bf16)
        // ---- stage tiles ----
#pragma unroll
        for (int t = 0; t < 2; t++) {
            int li = tid + t * 256;
            int r = li >> 2, q = li & 3;
            int grow = row0 + r;
            uint4 vh = make_uint4(0u, 0u, 0u, 0u), vl = vh;
            if (grow < N_NODES) {
                vh = xh4[(size_t)grow * 32 + k0 + q];
                vl = xl4[(size_t)grow * 32 + k0 + q];
            }
            *(uint4*)&As_h[r][q * 4] = vh;
            *(uint4*)&As_l[r][q * 4] = vl;
        }
        {
            int r = tid >> 2, q = tid & 3;
            *(uint4*)&Bs_h[r][q * 4] = wh4[(hd * 64 + r) * 32 + k0 + q];
            *(uint4*)&Bs_l[r][q * 4] = wl4[(hd * 64 + r) * 32 + k0 + q];
        }
        __syncthreads();

#pragma unroll
        for (int kt = 0; kt < 2; kt++) {
            const uint32_t koff = kt * 32;   // 8 words
            uint32_t ah[4], al[4];
            LDSM_X4(ah, aaddr_h + koff);
            LDSM_X4(al, aaddr_l + koff);
#pragma unroll
            for (int q = 0; q < 4; q++) {
                const uint32_t qoff = q * 1280 + koff;   // 16 rows * 20 words * 4B
                uint32_t bh[4], bl[4];
                LDSM_X4(bh, baddr_h + qoff);
                LDSM_X4(bl, baddr_l + qoff);
                MMA_BF16(acc[2*q],   ah[0], ah[1], ah[2], ah[3], bh[0], bh[1]);
                MMA_BF16(acc[2*q],   ah[0], ah[1], ah[2], ah[3], bl[0], bl[1]);
                MMA_BF16(acc[2*q],   al[0], al[1], al[2], al[3], bh[0], bh[1]);
                MMA_BF16(acc[2*q+1], ah[0], ah[1], ah[2], ah[3], bh[2], bh[3]);
                MMA_BF16(acc[2*q+1], ah[0], ah[1], ah[2], ah[3], bl[2], bl[3]);
                MMA_BF16(acc[2*q+1], al[0], al[1], al[2], al[3], bh[2], bh[3]);
            }
        }
        __syncthreads();
    }

    // ---- epilogue: fused attention dots + fp16 h store ----
    const int ra = row0 + w * 16 + g;
    const float* ac = a_vec + hd * 2 * OUT_F;
    float s0 = 0.f, s1 = 0.f, t0 = 0.f, t1 = 0.f;
#pragma unroll
    for (int j = 0; j < 8; j++) {
        int c = j * 8 + 2 * tig;
        float2 as = *(const float2*)(ac + c);
        float2 an = *(const float2*)(ac + OUT_F + c);
        s0 += acc[j][0] * as.x + acc[j][1] * as.y;
        s1 += acc[j][2] * as.x + acc[j][3] * as.y;
        t0 += acc[j][0] * an.x + acc[j][1] * an.y;
        t1 += acc[j][2] * an.x + acc[j][3] * an.y;
    }
#pragma unroll
    for (int o = 1; o < 4; o <<= 1) {
        s0 += __shfl_xor_sync(0xffffffffu, s0, o);
        s1 += __shfl_xor_sync(0xffffffffu, s1, o);
        t0 += __shfl_xor_sync(0xffffffffu, t0, o);
        t1 += __shfl_xor_sync(0xffffffffu, t1, o);
    }
    if (tig == 0) {
        if (ra < N_NODES) {
            g_aself[ra * N_HEADS + hd]  = s0;
            g_aneigh[ra * N_HEADS + hd] = t0;
        }
        if (ra + 8 < N_NODES) {
            g_aself[(ra + 8) * N_HEADS + hd]  = s1;
            g_aneigh[(ra + 8) * N_HEADS + hd] = t1;
        }
    }
    if (ra < N_NODES) {
        __half2* hp = (__half2*)(g_hh + (size_t)ra * HF + hd * OUT_F);
#pragma unroll
        for (int j = 0; j < 8; j++)
            hp[j * 4 + tig] = __floats2half2_rn(acc[j][0], acc[j][1]);
    }
    if (ra + 8 < N_NODES) {
        __half2* hp = (__half2*)(g_hh + (size_t)(ra + 8) * HF + hd * OUT_F);
#pragma unroll
        for (int j = 0; j < 8; j++)
            hp[j * 4 + tig] = __floats2half2_rn(acc[j][2], acc[j][3]);
    }
}

// ---------------- aggregation: warp per (dst, head), fp16 gather -------------
__global__ void k_agg(float* __restrict__ out) {
    int wid = threadIdx.x >> 5, lane = threadIdx.x & 31;
    int pair = blockIdx.x * 8 + wid;
    if (pair >= N_NODES * N_HEADS) return;
    int hd = pair / N_NODES;                   // head-major: L2 locality per head slice
    int n  = pair - hd * N_NODES;

    int s = g_offs[n], e = g_offs[n + 1];
    float acc0 = 0.f, acc1 = 0.f, den = 0.f;
    const __half2* hh2 = (const __half2*)g_hh;
    const int hoff = hd * 32 + lane;           // half2 index within node row

#pragma unroll 4
    for (int i = s; i < e; i++) {
        int   u = __ldg(&g_csr_src[i]);
        float wgt = __ldg(&g_csr_w[(size_t)i * 8 + hd]);
        __half2 v = hh2[(size_t)u * 256 + hoff];
        float2 f = __half22float2(v);
        acc0 = fmaf(wgt, f.x, acc0);
        acc1 = fmaf(wgt, f.y, acc1);
        den += wgt;
    }
    float inv = 1.f / (den + 1e-16f);
    float o0 = acc0 * inv, o1 = acc1 * inv;
    o0 = (o0 > 0.f) ? o0 : expm1f(o0);          // elu
    o1 = (o1 > 0.f) ? o1 : expm1f(o1);
    *(float2*)(out + (size_t)n * HF + hd * OUT_F + 2 * lane) = make_float2(o0, o1);
}

// ---------------- launch -----------------------------------------------------
extern "C" void kernel_launch(void* const* d_in, const int* in_sizes, int n_in,
                              void* d_out, int out_size) {
    const float* x   = (const float*)d_in[0];
    const int*   src = (const int*)d_in[1];
    const int*   dst = (const int*)d_in[2];
    const float* M   = (const float*)d_in[3];
    const float* W   = (const float*)d_in[4];
    const float* a   = (const float*)d_in[5];
    float* out = (float*)d_out;

    k_prep_x<<<(N_NODES * IN_F / 2 + 255) / 256, 256>>>(x);             // 0
    k_prep_w<<<(N_HEADS * OUT_F * IN_F + 255) / 256, 256>>>(W);         // 1
    k_zero_deg<<<(N_NODES + 255) / 256, 256>>>();                       // 2
    k_count<<<(N_EDGES + 255) / 256, 256>>>(dst);                       // 3
    k_scan<<<1, 1024>>>();                                              // 4
    k_gemm<<<dim3((N_NODES + 127) / 128, N_HEADS), 256>>>(a);           // 5
    k_fill<<<(N_EDGES + 255) / 256, 256>>>(src, dst, M);                // 6
    k_agg<<<N_NODES, 256>>>(out);                                       // 7
}

// round 5
// speedup vs baseline: 1.9317x; 1.2726x over previous
#include <cuda_runtime.h>
#include <cuda_bf16.h>
#include <cuda_fp16.h>
#include <stdint.h>
#include <math.h>

#define N_NODES 50000
#define N_EDGES 800000
#define IN_F    256
#define OUT_F   64
#define N_HEADS 8
#define HF      (N_HEADS * OUT_F)   // 512

// ---------------- device scratch ---------------------------------------------
__device__ __half g_hh[(size_t)N_NODES * HF];      // fp16 h for gather (~51 MB)
__device__ float g_aself[N_NODES * N_HEADS];
__device__ float g_aneigh[N_NODES * N_HEADS];
__device__ int   g_deg[N_NODES];
__device__ int   g_offs[N_NODES + 1];
__device__ int   g_cursor[N_NODES];
__device__ int   g_csr_src[N_EDGES];
__device__ float g_csr_w[(size_t)N_EDGES * N_HEADS];   // per-edge per-head exp weights
// bf16x3 split operands
__device__ __nv_bfloat16 g_xhi[(size_t)N_NODES * IN_F];
__device__ __nv_bfloat16 g_xlo[(size_t)N_NODES * IN_F];
__device__ __nv_bfloat16 g_wthi[N_HEADS * OUT_F * IN_F];   // [hd][n][k]
__device__ __nv_bfloat16 g_wtlo[N_HEADS * OUT_F * IN_F];

// ---------------- operand prep (fp32 -> bf16 hi/lo split) --------------------
__global__ void k_prep_x(const float* __restrict__ x) {
    int i = blockIdx.x * blockDim.x + threadIdx.x;
    const int total = N_NODES * IN_F / 2;
    if (i < total) {
        float2 v = ((const float2*)x)[i];
        __nv_bfloat16 h0 = __float2bfloat16_rn(v.x);
        __nv_bfloat16 h1 = __float2bfloat16_rn(v.y);
        __nv_bfloat16 l0 = __float2bfloat16_rn(v.x - __bfloat162float(h0));
        __nv_bfloat16 l1 = __float2bfloat16_rn(v.y - __bfloat162float(h1));
        ((__nv_bfloat162*)g_xhi)[i] = __halves2bfloat162(h0, h1);
        ((__nv_bfloat162*)g_xlo)[i] = __halves2bfloat162(l0, l1);
    }
}

__global__ void k_prep_w(const float* __restrict__ W) {
    int i = blockIdx.x * blockDim.x + threadIdx.x;          // [hd][n][k] linear
    if (i < N_HEADS * OUT_F * IN_F) {
        int k  = i & (IN_F - 1);
        int n  = (i >> 8) & (OUT_F - 1);
        int hd = i >> 14;
        float v = W[((size_t)hd * IN_F + k) * OUT_F + n];
        __nv_bfloat16 hi = __float2bfloat16_rn(v);
        __nv_bfloat16 lo = __float2bfloat16_rn(v - __bfloat162float(hi));
        g_wthi[i] = hi;
        g_wtlo[i] = lo;
    }
}

// ---------------- CSR build --------------------------------------------------
__global__ void k_zero_deg() {
    int i = blockIdx.x * blockDim.x + threadIdx.x;
    if (i < N_NODES) g_deg[i] = 0;
}

__global__ void k_count(const int* __restrict__ dst) {
    int e = blockIdx.x * blockDim.x + threadIdx.x;
    if (e < N_EDGES) atomicAdd(&g_deg[dst[e]], 1);
}

__global__ void k_scan() {
    __shared__ int warp_sums[32];
    int tid = threadIdx.x, lane = tid & 31, wid = tid >> 5;
    int carry = 0;
    for (int base = 0; base < N_NODES; base += 1024) {
        int i = base + tid;
        int v = (i < N_NODES) ? g_deg[i] : 0;
        int xsum = v;
#pragma unroll
        for (int o = 1; o < 32; o <<= 1) {
            int t = __shfl_up_sync(0xffffffffu, xsum, o);
            if (lane >= o) xsum += t;
        }
        if (lane == 31) warp_sums[wid] = xsum;
        __syncthreads();
        if (wid == 0) {
            int s = warp_sums[lane];
#pragma unroll
            for (int o = 1; o < 32; o <<= 1) {
                int t = __shfl_up_sync(0xffffffffu, s, o);
                if (lane >= o) s += t;
            }
            warp_sums[lane] = s;
        }
        __syncthreads();
        int woff = (wid == 0) ? 0 : warp_sums[wid - 1];
        int incl = xsum + woff;
        if (i < N_NODES) {
            int excl = carry + incl - v;
            g_offs[i]   = excl;
            g_cursor[i] = excl;
        }
        carry += warp_sums[31];
        __syncthreads();
    }
    if (tid == 0) g_offs[N_NODES] = carry;
}

// fill CSR + fused per-edge-head softmax numerators (after gemm: needs aself/aneigh)
__global__ void k_fill(const int* __restrict__ src, const int* __restrict__ dst,
                       const float* __restrict__ M) {
    int e = blockIdx.x * blockDim.x + threadIdx.x;
    if (e >= N_EDGES) return;
    int s = src[e], d = dst[e];
    float m = M[e];
    int p = atomicAdd(&g_cursor[d], 1);
    g_csr_src[p] = s;
    float4 as0 = *(const float4*)&g_aself[s * 8];
    float4 as1 = *(const float4*)&g_aself[s * 8 + 4];
    float4 an0 = *(const float4*)&g_aneigh[d * 8];
    float4 an1 = *(const float4*)&g_aneigh[d * 8 + 4];
    float ev[8] = {as0.x + an0.x, as0.y + an0.y, as0.z + an0.z, as0.w + an0.w,
                   as1.x + an1.x, as1.y + an1.y, as1.z + an1.z, as1.w + an1.w};
    float wv[8];
#pragma unroll
    for (int hd = 0; hd < 8; hd++) {
        float t = ev[hd];
        t = (t > 0.f) ? t : 0.2f * t;          // leaky_relu
        wv[hd] = __expf(t * m);
    }
    float4* wp = (float4*)&g_csr_w[(size_t)p * 8];
    wp[0] = make_float4(wv[0], wv[1], wv[2], wv[3]);
    wp[1] = make_float4(wv[4], wv[5], wv[6], wv[7]);
}

// ---------------- bf16x3 tensor-core GEMM + fused attention dots -------------
#define MMA_BF16(d, a0, a1, a2, a3, b0, b1)                                   \
    asm volatile(                                                             \
        "mma.sync.aligned.m16n8k16.row.col.f32.bf16.bf16.f32 "                \
        "{%0,%1,%2,%3}, {%4,%5,%6,%7}, {%8,%9}, {%0,%1,%2,%3};"               \
        : "+f"(d[0]), "+f"(d[1]), "+f"(d[2]), "+f"(d[3])                      \
        : "r"(a0), "r"(a1), "r"(a2), "r"(a3), "r"(b0), "r"(b1))

#define LDSM_X4(r, addr)                                                      \
    asm volatile("ldmatrix.sync.aligned.m8n8.x4.shared.b16 {%0,%1,%2,%3}, [%4];" \
        : "=r"((r)[0]), "=r"((r)[1]), "=r"((r)[2]), "=r"((r)[3]) : "r"(addr))

__global__ void __launch_bounds__(256, 2) k_gemm(const float* __restrict__ a_vec) {
    __shared__ uint32_t As_h[128][20], As_l[128][20];
    __shared__ uint32_t Bs_h[64][20],  Bs_l[64][20];

    const int tid  = threadIdx.x;
    const int w    = tid >> 5;
    const int lane = tid & 31;
    const int g    = lane >> 2;
    const int tig  = lane & 3;
    const int hd   = blockIdx.x;                 // head fastest: L2 x-tile reuse
    const int row0 = blockIdx.y * 128;

    float acc[8][4];
#pragma unroll
    for (int j = 0; j < 8; j++)
#pragma unroll
        for (int i = 0; i < 4; i++) acc[j][i] = 0.f;

    const int a_row  = w * 16 + (lane & 15);
    const int a_colw = (lane >> 4) * 4;
    uint32_t aaddr_h = (uint32_t)__cvta_generic_to_shared(&As_h[a_row][a_colw]);
    uint32_t aaddr_l = (uint32_t)__cvta_generic_to_shared(&As_l[a_row][a_colw]);
    const int b_row  = (lane & 7) + ((lane >> 4) << 3);
    const int b_colw = ((lane >> 3) & 1) * 4;
    uint32_t baddr_h = (uint32_t)__cvta_generic_to_shared(&Bs_h[b_row][b_colw]);
    uint32_t baddr_l = (uint32_t)__cvta_generic_to_shared(&Bs_l[b_row][b_colw]);

    const uint4* xh4 = (const uint4*)g_xhi;
    const uint4* xl4 = (const uint4*)g_xlo;
    const uint4* wh4 = (const uint4*)g_wthi;
    const uint4* wl4 = (const uint4*)g_wtlo;

    // per-thread tile-load coordinates
    const int rA0 = tid >> 2,          qA0 = tid & 3;          // li = tid
    const int rA1 = (tid + 256) >> 2,  qA1 = tid & 3;          // li = tid+256
    const int gr0 = row0 + rA0, gr1 = row0 + rA1;
    const int rB  = tid >> 2,          qB  = tid & 3;

    uint4 pAh0, pAl0, pAh1, pAl1, pBh, pBl;
    // prologue: fetch k0 = 0
    {
        uint4 z = make_uint4(0u, 0u, 0u, 0u);
        pAh0 = pAl0 = pAh1 = pAl1 = z;
        if (gr0 < N_NODES) { pAh0 = xh4[(size_t)gr0 * 32 + qA0]; pAl0 = xl4[(size_t)gr0 * 32 + qA0]; }
        if (gr1 < N_NODES) { pAh1 = xh4[(size_t)gr1 * 32 + qA1]; pAl1 = xl4[(size_t)gr1 * 32 + qA1]; }
        pBh = wh4[(hd * 64 + rB) * 32 + qB];
        pBl = wl4[(hd * 64 + rB) * 32 + qB];
    }

    for (int k0 = 0; k0 < 32; k0 += 4) {
        // ---- commit prefetched tile to smem ----
        *(uint4*)&As_h[rA0][qA0 * 4] = pAh0;
        *(uint4*)&As_l[rA0][qA0 * 4] = pAl0;
        *(uint4*)&As_h[rA1][qA1 * 4] = pAh1;
        *(uint4*)&As_l[rA1][qA1 * 4] = pAl1;
        *(uint4*)&Bs_h[rB][qB * 4]   = pBh;
        *(uint4*)&Bs_l[rB][qB * 4]   = pBl;
        __syncthreads();

        // ---- issue next tile's loads (overlap with MMA below) ----
        if (k0 + 4 < 32) {
            int kq = k0 + 4;
            if (gr0 < N_NODES) { pAh0 = xh4[(size_t)gr0 * 32 + kq + qA0]; pAl0 = xl4[(size_t)gr0 * 32 + kq + qA0]; }
            if (gr1 < N_NODES) { pAh1 = xh4[(size_t)gr1 * 32 + kq + qA1]; pAl1 = xl4[(size_t)gr1 * 32 + kq + qA1]; }
            pBh = wh4[(hd * 64 + rB) * 32 + kq + qB];
            pBl = wl4[(hd * 64 + rB) * 32 + kq + qB];
        }

#pragma unroll
        for (int kt = 0; kt < 2; kt++) {
            const uint32_t koff = kt * 32;   // 8 words
            uint32_t ah[4], al[4];
            LDSM_X4(ah, aaddr_h + koff);
            LDSM_X4(al, aaddr_l + koff);
#pragma unroll
            for (int q = 0; q < 4; q++) {
                const uint32_t qoff = q * 1280 + koff;   // 16 rows * 80B
                uint32_t bh[4], bl[4];
                LDSM_X4(bh, baddr_h + qoff);
                LDSM_X4(bl, baddr_l + qoff);
                MMA_BF16(acc[2*q],   ah[0], ah[1], ah[2], ah[3], bh[0], bh[1]);
                MMA_BF16(acc[2*q],   ah[0], ah[1], ah[2], ah[3], bl[0], bl[1]);
                MMA_BF16(acc[2*q],   al[0], al[1], al[2], al[3], bh[0], bh[1]);
                MMA_BF16(acc[2*q+1], ah[0], ah[1], ah[2], ah[3], bh[2], bh[3]);
                MMA_BF16(acc[2*q+1], ah[0], ah[1], ah[2], ah[3], bl[2], bl[3]);
                MMA_BF16(acc[2*q+1], al[0], al[1], al[2], al[3], bh[2], bh[3]);
            }
        }
        __syncthreads();
    }

    // ---- epilogue: fused attention dots + fp16 h store ----
    const int ra = row0 + w * 16 + g;
    const float* ac = a_vec + hd * 2 * OUT_F;
    float s0 = 0.f, s1 = 0.f, t0 = 0.f, t1 = 0.f;
#pragma unroll
    for (int j = 0; j < 8; j++) {
        int c = j * 8 + 2 * tig;
        float2 as = *(const float2*)(ac + c);
        float2 an = *(const float2*)(ac + OUT_F + c);
        s0 += acc[j][0] * as.x + acc[j][1] * as.y;
        s1 += acc[j][2] * as.x + acc[j][3] * as.y;
        t0 += acc[j][0] * an.x + acc[j][1] * an.y;
        t1 += acc[j][2] * an.x + acc[j][3] * an.y;
    }
#pragma unroll
    for (int o = 1; o < 4; o <<= 1) {
        s0 += __shfl_xor_sync(0xffffffffu, s0, o);
        s1 += __shfl_xor_sync(0xffffffffu, s1, o);
        t0 += __shfl_xor_sync(0xffffffffu, t0, o);
        t1 += __shfl_xor_sync(0xffffffffu, t1, o);
    }
    if (tig == 0) {
        if (ra < N_NODES) {
            g_aself[ra * N_HEADS + hd]  = s0;
            g_aneigh[ra * N_HEADS + hd] = t0;
        }
        if (ra + 8 < N_NODES) {
            g_aself[(ra + 8) * N_HEADS + hd]  = s1;
            g_aneigh[(ra + 8) * N_HEADS + hd] = t1;
        }
    }
    if (ra < N_NODES) {
        __half2* hp = (__half2*)(g_hh + (size_t)ra * HF + hd * OUT_F);
#pragma unroll
        for (int j = 0; j < 8; j++)
            hp[j * 4 + tig] = __floats2half2_rn(acc[j][0], acc[j][1]);
    }
    if (ra + 8 < N_NODES) {
        __half2* hp = (__half2*)(g_hh + (size_t)(ra + 8) * HF + hd * OUT_F);
#pragma unroll
        for (int j = 0; j < 8; j++)
            hp[j * 4 + tig] = __floats2half2_rn(acc[j][2], acc[j][3]);
    }
}

// ---------------- aggregation: one warp per node, ALL 8 heads ----------------
// lane covers 16 contiguous fp16 cols [lane*16, lane*16+16) => head = lane>>2
__global__ void k_agg(float* __restrict__ out) {
    int wid = threadIdx.x >> 5, lane = threadIdx.x & 31;
    int n = blockIdx.x * 8 + wid;
    if (n >= N_NODES) return;

    int s = g_offs[n], e = g_offs[n + 1];
    const uint4* hh4 = (const uint4*)g_hh;          // 64 uint4 per node row
    const int vi = lane * 2;                        // this lane's uint4 pair
    const int hsel = lane >> 2;                     // head for csr_w pick

    float acc[16];
#pragma unroll
    for (int j = 0; j < 16; j++) acc[j] = 0.f;
    float den = 0.f;

    for (int i = s; i < e; i++) {
        int   u   = __ldg(&g_csr_src[i]);
        float wgt = __ldg(&g_csr_w[(size_t)i * 8 + hsel]);
        uint4 v0 = hh4[(size_t)u * 64 + vi];
        uint4 v1 = hh4[(size_t)u * 64 + vi + 1];
        den += wgt;
        const __half2* p0 = (const __half2*)&v0;
        const __half2* p1 = (const __half2*)&v1;
#pragma unroll
        for (int j = 0; j < 4; j++) {
            float2 f0 = __half22float2(p0[j]);
            float2 f1 = __half22float2(p1[j]);
            acc[2*j]     = fmaf(wgt, f0.x, acc[2*j]);
            acc[2*j+1]   = fmaf(wgt, f0.y, acc[2*j+1]);
            acc[8+2*j]   = fmaf(wgt, f1.x, acc[8+2*j]);
            acc[8+2*j+1] = fmaf(wgt, f1.y, acc[8+2*j+1]);
        }
    }
    float inv = 1.f / (den + 1e-16f);
    float* op = out + (size_t)n * HF + lane * 16;
#pragma unroll
    for (int j = 0; j < 16; j++) {
        float v = acc[j] * inv;
        acc[j] = (v > 0.f) ? v : expm1f(v);         // elu
    }
#pragma unroll
    for (int j = 0; j < 4; j++)
        *(float4*)(op + j * 4) = make_float4(acc[4*j], acc[4*j+1], acc[4*j+2], acc[4*j+3]);
}

// ---------------- launch -----------------------------------------------------
extern "C" void kernel_launch(void* const* d_in, const int* in_sizes, int n_in,
                              void* d_out, int out_size) {
    const float* x   = (const float*)d_in[0];
    const int*   src = (const int*)d_in[1];
    const int*   dst = (const int*)d_in[2];
    const float* M   = (const float*)d_in[3];
    const float* W   = (const float*)d_in[4];
    const float* a   = (const float*)d_in[5];
    float* out = (float*)d_out;

    k_prep_x<<<(N_NODES * IN_F / 2 + 255) / 256, 256>>>(x);             // 0
    k_prep_w<<<(N_HEADS * OUT_F * IN_F + 255) / 256, 256>>>(W);         // 1
    k_zero_deg<<<(N_NODES + 255) / 256, 256>>>();                       // 2
    k_count<<<(N_EDGES + 255) / 256, 256>>>(dst);                       // 3
    k_scan<<<1, 1024>>>();                                              // 4
    k_gemm<<<dim3(N_HEADS, (N_NODES + 127) / 128), 256>>>(a);           // 5
    k_fill<<<(N_EDGES + 255) / 256, 256>>>(src, dst, M);                // 6
    k_agg<<<(N_NODES + 7) / 8, 256>>>(out);                             // 7
}

// round 7
// speedup vs baseline: 2.2021x; 1.1400x over previous
#include <cuda_runtime.h>
#include <cuda_bf16.h>
#include <cuda_fp16.h>
#include <stdint.h>
#include <math.h>

#define N_NODES 50000
#define N_EDGES 800000
#define IN_F    256
#define OUT_F   64
#define N_HEADS 8
#define HF      (N_HEADS * OUT_F)   // 512

// ---------------- device scratch ---------------------------------------------
__device__ __half g_hh[(size_t)N_NODES * HF];      // fp16 h for gather (~51 MB)
__device__ float g_aself[N_NODES * N_HEADS];
__device__ float g_aneigh[N_NODES * N_HEADS];
__device__ int   g_deg[N_NODES];
__device__ int   g_offs[N_NODES + 1];
__device__ int   g_cursor[N_NODES];
__device__ int   g_csr_src[N_EDGES];
__device__ float g_csr_m[N_EDGES];
// bf16x3 split operands
__device__ __nv_bfloat16 g_xhi[(size_t)N_NODES * IN_F];
__device__ __nv_bfloat16 g_xlo[(size_t)N_NODES * IN_F];
__device__ __nv_bfloat16 g_wthi[N_HEADS * OUT_F * IN_F];   // [hd][n][k]
__device__ __nv_bfloat16 g_wtlo[N_HEADS * OUT_F * IN_F];

// ---------------- operand prep (fp32 -> bf16 hi/lo split) --------------------
__global__ void k_prep_x(const float* __restrict__ x) {
    int i = blockIdx.x * blockDim.x + threadIdx.x;
    const int total = N_NODES * IN_F / 2;
    if (i < total) {
        float2 v = ((const float2*)x)[i];
        __nv_bfloat16 h0 = __float2bfloat16_rn(v.x);
        __nv_bfloat16 h1 = __float2bfloat16_rn(v.y);
        __nv_bfloat16 l0 = __float2bfloat16_rn(v.x - __bfloat162float(h0));
        __nv_bfloat16 l1 = __float2bfloat16_rn(v.y - __bfloat162float(h1));
        ((__nv_bfloat162*)g_xhi)[i] = __halves2bfloat162(h0, h1);
        ((__nv_bfloat162*)g_xlo)[i] = __halves2bfloat162(l0, l1);
    }
}

__global__ void k_prep_w(const float* __restrict__ W) {
    int i = blockIdx.x * blockDim.x + threadIdx.x;          // [hd][n][k] linear
    if (i < N_HEADS * OUT_F * IN_F) {
        int k  = i & (IN_F - 1);
        int n  = (i >> 8) & (OUT_F - 1);
        int hd = i >> 14;
        float v = W[((size_t)hd * IN_F + k) * OUT_F + n];
        __nv_bfloat16 hi = __float2bfloat16_rn(v);
        __nv_bfloat16 lo = __float2bfloat16_rn(v - __bfloat162float(hi));
        g_wthi[i] = hi;
        g_wtlo[i] = lo;
    }
}

// ---------------- CSR build --------------------------------------------------
__global__ void k_zero_deg() {
    int i = blockIdx.x * blockDim.x + threadIdx.x;
    if (i < N_NODES) g_deg[i] = 0;
}

__global__ void k_count(const int* __restrict__ dst) {
    int e = blockIdx.x * blockDim.x + threadIdx.x;
    if (e < N_EDGES) atomicAdd(&g_deg[dst[e]], 1);
}

__global__ void k_scan() {
    __shared__ int warp_sums[32];
    int tid = threadIdx.x, lane = tid & 31, wid = tid >> 5;
    int carry = 0;
    for (int base = 0; base < N_NODES; base += 1024) {
        int i = base + tid;
        int v = (i < N_NODES) ? g_deg[i] : 0;
        int xsum = v;
#pragma unroll
        for (int o = 1; o < 32; o <<= 1) {
            int t = __shfl_up_sync(0xffffffffu, xsum, o);
            if (lane >= o) xsum += t;
        }
        if (lane == 31) warp_sums[wid] = xsum;
        __syncthreads();
        if (wid == 0) {
            int s = warp_sums[lane];
#pragma unroll
            for (int o = 1; o < 32; o <<= 1) {
                int t = __shfl_up_sync(0xffffffffu, s, o);
                if (lane >= o) s += t;
            }
            warp_sums[lane] = s;
        }
        __syncthreads();
        int woff = (wid == 0) ? 0 : warp_sums[wid - 1];
        int incl = xsum + woff;
        if (i < N_NODES) {
            int excl = carry + incl - v;
            g_offs[i]   = excl;
            g_cursor[i] = excl;
        }
        carry += warp_sums[31];
        __syncthreads();
    }
    if (tid == 0) g_offs[N_NODES] = carry;
}

// fill CSR: (src, m) only — 8 B/edge scattered
__global__ void k_fill(const int* __restrict__ src, const int* __restrict__ dst,
                       const float* __restrict__ M) {
    int e = blockIdx.x * blockDim.x + threadIdx.x;
    if (e >= N_EDGES) return;
    int d = dst[e];
    int p = atomicAdd(&g_cursor[d], 1);
    g_csr_src[p] = src[e];
    g_csr_m[p]   = M[e];
}

// ---------------- bf16x3 mma.sync GEMM, cp.async double-buffered -------------
#define MMA_BF16(d, a0, a1, a2, a3, b0, b1)                                   \
    asm volatile(                                                             \
        "mma.sync.aligned.m16n8k16.row.col.f32.bf16.bf16.f32 "                \
        "{%0,%1,%2,%3}, {%4,%5,%6,%7}, {%8,%9}, {%0,%1,%2,%3};"               \
        : "+f"(d[0]), "+f"(d[1]), "+f"(d[2]), "+f"(d[3])                      \
        : "r"(a0), "r"(a1), "r"(a2), "r"(a3), "r"(b0), "r"(b1))

#define LDSM_X4(r, addr)                                                      \
    asm volatile("ldmatrix.sync.aligned.m8n8.x4.shared.b16 {%0,%1,%2,%3}, [%4];" \
        : "=r"((r)[0]), "=r"((r)[1]), "=r"((r)[2]), "=r"((r)[3]) : "r"(addr))

#define CP16(dst, src, sz)                                                    \
    asm volatile("cp.async.cg.shared.global [%0], [%1], 16, %2;"              \
        :: "r"(dst), "l"(src), "r"(sz) : "memory")
#define CP_COMMIT() asm volatile("cp.async.commit_group;" ::: "memory")

// smem stage layout (bytes): rows padded to 20 words (80B)
#define OFF_AH 0
#define OFF_AL 10240
#define OFF_BH 20480
#define OFF_BL 25600
#define STAGE  30720
#define GEMM_SMEM (2 * STAGE)

__global__ void __launch_bounds__(256, 3) k_gemm(const float* __restrict__ a_vec) {
    extern __shared__ char smem[];
    const uint32_t sb = (uint32_t)__cvta_generic_to_shared(smem);

    const int tid  = threadIdx.x;
    const int w    = tid >> 5;
    const int lane = tid & 31;
    const int g    = lane >> 2;
    const int tig  = lane & 3;
    const int hd   = blockIdx.x;                 // head fastest: L2 x reuse
    const int row0 = blockIdx.y * 128;

    float acc[8][4];
#pragma unroll
    for (int j = 0; j < 8; j++)
#pragma unroll
        for (int i = 0; i < 4; i++) acc[j][i] = 0.f;

    // ldmatrix per-lane base offsets (within a stage)
    const int a_row  = w * 16 + (lane & 15);
    const int a_colw = (lane >> 4) * 4;
    const uint32_t aoff_h = OFF_AH + (uint32_t)(a_row * 20 + a_colw) * 4;
    const uint32_t aoff_l = OFF_AL + (uint32_t)(a_row * 20 + a_colw) * 4;
    const int b_row  = (lane & 7) + ((lane >> 4) << 3);
    const int b_colw = ((lane >> 3) & 1) * 4;
    const uint32_t boff_h = OFF_BH + (uint32_t)(b_row * 20 + b_colw) * 4;
    const uint32_t boff_l = OFF_BL + (uint32_t)(b_row * 20 + b_colw) * 4;

    const uint4* xh4 = (const uint4*)g_xhi;      // 32 uint4 per x row
    const uint4* xl4 = (const uint4*)g_xlo;
    const uint4* wh4 = (const uint4*)g_wthi;
    const uint4* wl4 = (const uint4*)g_wtlo;

    // per-thread cp.async assignments
    const int rA0 = tid >> 2,         qA0 = tid & 3;          // i = tid
    const int rA1 = (tid + 256) >> 2, qA1 = tid & 3;          // i = tid + 256
    const int gr0 = row0 + rA0, gr1 = row0 + rA1;
    const int szA0 = (gr0 < N_NODES) ? 16 : 0;
    const int szA1 = (gr1 < N_NODES) ? 16 : 0;
    const size_t sr0 = (size_t)((gr0 < N_NODES) ? gr0 : 0) * 32;
    const size_t sr1 = (size_t)((gr1 < N_NODES) ? gr1 : 0) * 32;
    const int rB = tid >> 2, qB = tid & 3;
    const size_t srB = (size_t)(hd * 64 + rB) * 32;
    const uint32_t dA0 = (uint32_t)(rA0 * 80 + qA0 * 16);
    const uint32_t dA1 = (uint32_t)(rA1 * 80 + qA1 * 16);
    const uint32_t dB  = (uint32_t)(rB * 80 + qB * 16);

    // issue loads for k-tile kit into stage st
#define ISSUE_TILE(st, kit)                                                   \
    do {                                                                      \
        const int kw = (kit) * 4;                                             \
        const uint32_t base = sb + (st) * STAGE;                              \
        CP16(base + OFF_AH + dA0, xh4 + sr0 + kw + qA0, szA0);                \
        CP16(base + OFF_AL + dA0, xl4 + sr0 + kw + qA0, szA0);                \
        CP16(base + OFF_AH + dA1, xh4 + sr1 + kw + qA1, szA1);                \
        CP16(base + OFF_AL + dA1, xl4 + sr1 + kw + qA1, szA1);                \
        CP16(base + OFF_BH + dB,  wh4 + srB + kw + qB, 16);                   \
        CP16(base + OFF_BL + dB,  wl4 + srB + kw + qB, 16);                   \
        CP_COMMIT();                                                          \
    } while (0)

    ISSUE_TILE(0, 0);

    for (int kit = 0; kit < 8; kit++) {
        const int st = kit & 1;
        if (kit + 1 < 8) {
            ISSUE_TILE(st ^ 1, kit + 1);
            asm volatile("cp.async.wait_group 1;" ::: "memory");
        } else {
            asm volatile("cp.async.wait_group 0;" ::: "memory");
        }
        __syncthreads();

        const uint32_t sbase = st * STAGE + sb;
#pragma unroll
        for (int kt = 0; kt < 2; kt++) {
            const uint32_t koff = kt * 32;       // 8 words
            uint32_t ah[4], al[4];
            LDSM_X4(ah, sbase + aoff_h + koff);
            LDSM_X4(al, sbase + aoff_l + koff);
#pragma unroll
            for (int q = 0; q < 4; q++) {
                const uint32_t qoff = q * 1280 + koff;   // 16 rows * 80B
                uint32_t bh[4], bl[4];
                LDSM_X4(bh, sbase + boff_h + qoff);
                LDSM_X4(bl, sbase + boff_l + qoff);
                MMA_BF16(acc[2*q],   ah[0], ah[1], ah[2], ah[3], bh[0], bh[1]);
                MMA_BF16(acc[2*q],   ah[0], ah[1], ah[2], ah[3], bl[0], bl[1]);
                MMA_BF16(acc[2*q],   al[0], al[1], al[2], al[3], bh[0], bh[1]);
                MMA_BF16(acc[2*q+1], ah[0], ah[1], ah[2], ah[3], bh[2], bh[3]);
                MMA_BF16(acc[2*q+1], ah[0], ah[1], ah[2], ah[3], bl[2], bl[3]);
                MMA_BF16(acc[2*q+1], al[0], al[1], al[2], al[3], bh[2], bh[3]);
            }
        }
        __syncthreads();   // stage safe to overwrite next iteration
    }

    // ---- epilogue: fused attention dots + fp16 h store ----
    const int ra = row0 + w * 16 + g;
    const float* ac = a_vec + hd * 2 * OUT_F;
    float s0 = 0.f, s1 = 0.f, t0 = 0.f, t1 = 0.f;
#pragma unroll
    for (int j = 0; j < 8; j++) {
        int c = j * 8 + 2 * tig;
        float2 as = *(const float2*)(ac + c);
        float2 an = *(const float2*)(ac + OUT_F + c);
        s0 += acc[j][0] * as.x + acc[j][1] * as.y;
        s1 += acc[j][2] * as.x + acc[j][3] * as.y;
        t0 += acc[j][0] * an.x + acc[j][1] * an.y;
        t1 += acc[j][2] * an.x + acc[j][3] * an.y;
    }
#pragma unroll
    for (int o = 1; o < 4; o <<= 1) {
        s0 += __shfl_xor_sync(0xffffffffu, s0, o);
        s1 += __shfl_xor_sync(0xffffffffu, s1, o);
        t0 += __shfl_xor_sync(0xffffffffu, t0, o);
        t1 += __shfl_xor_sync(0xffffffffu, t1, o);
    }
    if (tig == 0) {
        if (ra < N_NODES) {
            g_aself[ra * N_HEADS + hd]  = s0;
            g_aneigh[ra * N_HEADS + hd] = t0;
        }
        if (ra + 8 < N_NODES) {
            g_aself[(ra + 8) * N_HEADS + hd]  = s1;
            g_aneigh[(ra + 8) * N_HEADS + hd] = t1;
        }
    }
    if (ra < N_NODES) {
        __half2* hp = (__half2*)(g_hh + (size_t)ra * HF + hd * OUT_F);
#pragma unroll
        for (int j = 0; j < 8; j++)
            hp[j * 4 + tig] = __floats2half2_rn(acc[j][0], acc[j][1]);
    }
    if (ra + 8 < N_NODES) {
        __half2* hp = (__half2*)(g_hh + (size_t)(ra + 8) * HF + hd * OUT_F);
#pragma unroll
        for (int j = 0; j < 8; j++)
            hp[j * 4 + tig] = __floats2half2_rn(acc[j][2], acc[j][3]);
    }
}

// ---------------- aggregation: one warp per node, ALL 8 heads ----------------
// lane covers 16 contiguous fp16 cols [lane*16, lane*16+16) => head = lane>>2.
// leaky_relu + exp computed inline per lane (no g_csr_w pass).
__global__ void k_agg(float* __restrict__ out) {
    int wid = threadIdx.x >> 5, lane = threadIdx.x & 31;
    int n = blockIdx.x * 8 + wid;
    if (n >= N_NODES) return;

    int s = g_offs[n], e = g_offs[n + 1];
    const uint4* hh4 = (const uint4*)g_hh;          // 64 uint4 per node row
    const int vi = lane * 2;
    const int hsel = lane >> 2;
    const float an = __ldg(&g_aneigh[n * 8 + hsel]);

    float acc[16];
#pragma unroll
    for (int j = 0; j < 16; j++) acc[j] = 0.f;
    float den = 0.f;

    int u = 0; float m = 0.f;
    if (s < e) { u = __ldg(&g_csr_src[s]); m = __ldg(&g_csr_m[s]); }
    for (int i = s; i < e; i++) {
        int uc = u; float mc = m;
        if (i + 1 < e) { u = __ldg(&g_csr_src[i + 1]); m = __ldg(&g_csr_m[i + 1]); }
        float ev = __ldg(&g_aself[uc * 8 + hsel]) + an;
        ev = (ev > 0.f) ? ev : 0.2f * ev;           // leaky_relu
        float wgt = __expf(ev * mc);
        uint4 v0 = hh4[(size_t)uc * 64 + vi];
        uint4 v1 = hh4[(size_t)uc * 64 + vi + 1];
        den += wgt;
        const __half2* p0 = (const __half2*)&v0;
        const __half2* p1 = (const __half2*)&v1;
#pragma unroll
        for (int j = 0; j < 4; j++) {
            float2 f0 = __half22float2(p0[j]);
            float2 f1 = __half22float2(p1[j]);
            acc[2*j]     = fmaf(wgt, f0.x, acc[2*j]);
            acc[2*j+1]   = fmaf(wgt, f0.y, acc[2*j+1]);
            acc[8+2*j]   = fmaf(wgt, f1.x, acc[8+2*j]);
            acc[8+2*j+1] = fmaf(wgt, f1.y, acc[8+2*j+1]);
        }
    }
    float inv = 1.f / (den + 1e-16f);
    float* op = out + (size_t)n * HF + lane * 16;
#pragma unroll
    for (int j = 0; j < 16; j++) {
        float v = acc[j] * inv;
        acc[j] = (v > 0.f) ? v : expm1f(v);         // elu
    }
#pragma unroll
    for (int j = 0; j < 4; j++)
        *(float4*)(op + j * 4) = make_float4(acc[4*j], acc[4*j+1], acc[4*j+2], acc[4*j+3]);
}

// ---------------- launch -----------------------------------------------------
extern "C" void kernel_launch(void* const* d_in, const int* in_sizes, int n_in,
                              void* d_out, int out_size) {
    const float* x   = (const float*)d_in[0];
    const int*   src = (const int*)d_in[1];
    const int*   dst = (const int*)d_in[2];
    const float* M   = (const float*)d_in[3];
    const float* W   = (const float*)d_in[4];
    const float* a   = (const float*)d_in[5];
    float* out = (float*)d_out;

    cudaFuncSetAttribute(k_gemm, cudaFuncAttributeMaxDynamicSharedMemorySize,
                         GEMM_SMEM);

    k_prep_x<<<(N_NODES * IN_F / 2 + 255) / 256, 256>>>(x);             // 0
    k_prep_w<<<(N_HEADS * OUT_F * IN_F + 255) / 256, 256>>>(W);         // 1
    k_zero_deg<<<(N_NODES + 255) / 256, 256>>>();                       // 2
    k_count<<<(N_EDGES + 255) / 256, 256>>>(dst);                       // 3
    k_scan<<<1, 1024>>>();                                              // 4
    k_gemm<<<dim3(N_HEADS, (N_NODES + 127) / 128), 256, GEMM_SMEM>>>(a);// 5
    k_fill<<<(N_EDGES + 255) / 256, 256>>>(src, dst, M);                // 6
    k_agg<<<(N_NODES + 7) / 8, 256>>>(out);                             // 7
}

// round 8
// speedup vs baseline: 2.2969x; 1.0430x over previous
#include <cuda_runtime.h>
#include <cuda_bf16.h>
#include <cuda_fp16.h>
#include <stdint.h>
#include <math.h>

#define N_NODES 50000
#define N_EDGES 800000
#define IN_F    256
#define OUT_F   64
#define N_HEADS 8
#define HF      (N_HEADS * OUT_F)   // 512

// ---------------- device scratch ---------------------------------------------
__device__ __half g_hh[(size_t)N_NODES * HF];      // fp16 h for gather (~51 MB)
__device__ float g_aself[N_NODES * N_HEADS];
__device__ float g_aneigh[N_NODES * N_HEADS];
__device__ int   g_deg[N_NODES];
__device__ int   g_offs[N_NODES + 1];
__device__ int   g_cursor[N_NODES];
__device__ int   g_csr_src[N_EDGES];
__device__ float g_csr_m[N_EDGES];
// bf16x3 split operands
__device__ __nv_bfloat16 g_xhi[(size_t)N_NODES * IN_F];
__device__ __nv_bfloat16 g_xlo[(size_t)N_NODES * IN_F];
__device__ __nv_bfloat16 g_wthi[N_HEADS * OUT_F * IN_F];   // [hd][n][k]
__device__ __nv_bfloat16 g_wtlo[N_HEADS * OUT_F * IN_F];

// ---------------- operand prep (fp32 -> bf16 hi/lo split) --------------------
__global__ void k_prep_x(const float* __restrict__ x) {
    int i = blockIdx.x * blockDim.x + threadIdx.x;
    const int total = N_NODES * IN_F / 2;
    if (i < total) {
        float2 v = ((const float2*)x)[i];
        __nv_bfloat16 h0 = __float2bfloat16_rn(v.x);
        __nv_bfloat16 h1 = __float2bfloat16_rn(v.y);
        __nv_bfloat16 l0 = __float2bfloat16_rn(v.x - __bfloat162float(h0));
        __nv_bfloat16 l1 = __float2bfloat16_rn(v.y - __bfloat162float(h1));
        ((__nv_bfloat162*)g_xhi)[i] = __halves2bfloat162(h0, h1);
        ((__nv_bfloat162*)g_xlo)[i] = __halves2bfloat162(l0, l1);
    }
}

__global__ void k_prep_w(const float* __restrict__ W) {
    int i = blockIdx.x * blockDim.x + threadIdx.x;          // [hd][n][k] linear
    if (i < N_HEADS * OUT_F * IN_F) {
        int k  = i & (IN_F - 1);
        int n  = (i >> 8) & (OUT_F - 1);
        int hd = i >> 14;
        float v = W[((size_t)hd * IN_F + k) * OUT_F + n];
        __nv_bfloat16 hi = __float2bfloat16_rn(v);
        __nv_bfloat16 lo = __float2bfloat16_rn(v - __bfloat162float(hi));
        g_wthi[i] = hi;
        g_wtlo[i] = lo;
    }
}

// ---------------- CSR build --------------------------------------------------
__global__ void k_zero_deg() {
    int i = blockIdx.x * blockDim.x + threadIdx.x;
    if (i < N_NODES) g_deg[i] = 0;
}

__global__ void k_count(const int* __restrict__ dst) {
    int e = blockIdx.x * blockDim.x + threadIdx.x;
    if (e < N_EDGES) atomicAdd(&g_deg[dst[e]], 1);
}

__global__ void k_scan() {
    __shared__ int warp_sums[32];
    int tid = threadIdx.x, lane = tid & 31, wid = tid >> 5;
    int carry = 0;
    for (int base = 0; base < N_NODES; base += 1024) {
        int i = base + tid;
        int v = (i < N_NODES) ? g_deg[i] : 0;
        int xsum = v;
#pragma unroll
        for (int o = 1; o < 32; o <<= 1) {
            int t = __shfl_up_sync(0xffffffffu, xsum, o);
            if (lane >= o) xsum += t;
        }
        if (lane == 31) warp_sums[wid] = xsum;
        __syncthreads();
        if (wid == 0) {
            int s = warp_sums[lane];
#pragma unroll
            for (int o = 1; o < 32; o <<= 1) {
                int t = __shfl_up_sync(0xffffffffu, s, o);
                if (lane >= o) s += t;
            }
            warp_sums[lane] = s;
        }
        __syncthreads();
        int woff = (wid == 0) ? 0 : warp_sums[wid - 1];
        int incl = xsum + woff;
        if (i < N_NODES) {
            int excl = carry + incl - v;
            g_offs[i]   = excl;
            g_cursor[i] = excl;
        }
        carry += warp_sums[31];
        __syncthreads();
    }
    if (tid == 0) g_offs[N_NODES] = carry;
}

// fill CSR: (src, m) only — 8 B/edge scattered
__global__ void k_fill(const int* __restrict__ src, const int* __restrict__ dst,
                       const float* __restrict__ M) {
    int e = blockIdx.x * blockDim.x + threadIdx.x;
    if (e >= N_EDGES) return;
    int d = dst[e];
    int p = atomicAdd(&g_cursor[d], 1);
    g_csr_src[p] = src[e];
    g_csr_m[p]   = M[e];
}

// ---------------- bf16x3 mma.sync GEMM, cp.async double-buffered -------------
#define MMA_BF16(d, a0, a1, a2, a3, b0, b1)                                   \
    asm volatile(                                                             \
        "mma.sync.aligned.m16n8k16.row.col.f32.bf16.bf16.f32 "                \
        "{%0,%1,%2,%3}, {%4,%5,%6,%7}, {%8,%9}, {%0,%1,%2,%3};"               \
        : "+f"(d[0]), "+f"(d[1]), "+f"(d[2]), "+f"(d[3])                      \
        : "r"(a0), "r"(a1), "r"(a2), "r"(a3), "r"(b0), "r"(b1))

#define LDSM_X4(r, addr)                                                      \
    asm volatile("ldmatrix.sync.aligned.m8n8.x4.shared.b16 {%0,%1,%2,%3}, [%4];" \
        : "=r"((r)[0]), "=r"((r)[1]), "=r"((r)[2]), "=r"((r)[3]) : "r"(addr))

#define CP16(dst, src, sz)                                                    \
    asm volatile("cp.async.cg.shared.global [%0], [%1], 16, %2;"              \
        :: "r"(dst), "l"(src), "r"(sz) : "memory")
#define CP_COMMIT() asm volatile("cp.async.commit_group;" ::: "memory")

// smem stage layout (bytes): rows padded to 20 words (80B)
#define OFF_AH 0
#define OFF_AL 10240
#define OFF_BH 20480
#define OFF_BL 25600
#define STAGE  30720
#define GEMM_SMEM (2 * STAGE)

__global__ void __launch_bounds__(256, 3) k_gemm(const float* __restrict__ a_vec) {
    extern __shared__ char smem[];
    const uint32_t sb = (uint32_t)__cvta_generic_to_shared(smem);

    const int tid  = threadIdx.x;
    const int w    = tid >> 5;
    const int lane = tid & 31;
    const int g    = lane >> 2;
    const int tig  = lane & 3;
    const int hd   = blockIdx.x;                 // head fastest: L2 x reuse
    const int row0 = blockIdx.y * 128;

    float acc[8][4];
#pragma unroll
    for (int j = 0; j < 8; j++)
#pragma unroll
        for (int i = 0; i < 4; i++) acc[j][i] = 0.f;

    // ldmatrix per-lane base offsets (within a stage)
    const int a_row  = w * 16 + (lane & 15);
    const int a_colw = (lane >> 4) * 4;
    const uint32_t aoff_h = OFF_AH + (uint32_t)(a_row * 20 + a_colw) * 4;
    const uint32_t aoff_l = OFF_AL + (uint32_t)(a_row * 20 + a_colw) * 4;
    const int b_row  = (lane & 7) + ((lane >> 4) << 3);
    const int b_colw = ((lane >> 3) & 1) * 4;
    const uint32_t boff_h = OFF_BH + (uint32_t)(b_row * 20 + b_colw) * 4;
    const uint32_t boff_l = OFF_BL + (uint32_t)(b_row * 20 + b_colw) * 4;

    const uint4* xh4 = (const uint4*)g_xhi;      // 32 uint4 per x row
    const uint4* xl4 = (const uint4*)g_xlo;
    const uint4* wh4 = (const uint4*)g_wthi;
    const uint4* wl4 = (const uint4*)g_wtlo;

    // per-thread cp.async assignments
    const int rA0 = tid >> 2,         qA0 = tid & 3;          // i = tid
    const int rA1 = (tid + 256) >> 2, qA1 = tid & 3;          // i = tid + 256
    const int gr0 = row0 + rA0, gr1 = row0 + rA1;
    const int szA0 = (gr0 < N_NODES) ? 16 : 0;
    const int szA1 = (gr1 < N_NODES) ? 16 : 0;
    const size_t sr0 = (size_t)((gr0 < N_NODES) ? gr0 : 0) * 32;
    const size_t sr1 = (size_t)((gr1 < N_NODES) ? gr1 : 0) * 32;
    const int rB = tid >> 2, qB = tid & 3;
    const size_t srB = (size_t)(hd * 64 + rB) * 32;
    const uint32_t dA0 = (uint32_t)(rA0 * 80 + qA0 * 16);
    const uint32_t dA1 = (uint32_t)(rA1 * 80 + qA1 * 16);
    const uint32_t dB  = (uint32_t)(rB * 80 + qB * 16);

#define ISSUE_TILE(st, kit)                                                   \
    do {                                                                      \
        const int kw = (kit) * 4;                                             \
        const uint32_t base = sb + (st) * STAGE;                              \
        CP16(base + OFF_AH + dA0, xh4 + sr0 + kw + qA0, szA0);                \
        CP16(base + OFF_AL + dA0, xl4 + sr0 + kw + qA0, szA0);                \
        CP16(base + OFF_AH + dA1, xh4 + sr1 + kw + qA1, szA1);                \
        CP16(base + OFF_AL + dA1, xl4 + sr1 + kw + qA1, szA1);                \
        CP16(base + OFF_BH + dB,  wh4 + srB + kw + qB, 16);                   \
        CP16(base + OFF_BL + dB,  wl4 + srB + kw + qB, 16);                   \
        CP_COMMIT();                                                          \
    } while (0)

    ISSUE_TILE(0, 0);

    for (int kit = 0; kit < 8; kit++) {
        const int st = kit & 1;
        if (kit + 1 < 8) {
            ISSUE_TILE(st ^ 1, kit + 1);
            asm volatile("cp.async.wait_group 1;" ::: "memory");
        } else {
            asm volatile("cp.async.wait_group 0;" ::: "memory");
        }
        __syncthreads();

        const uint32_t sbase = st * STAGE + sb;
#pragma unroll
        for (int kt = 0; kt < 2; kt++) {
            const uint32_t koff = kt * 32;       // 8 words
            uint32_t ah[4], al[4];
            LDSM_X4(ah, sbase + aoff_h + koff);
            LDSM_X4(al, sbase + aoff_l + koff);
#pragma unroll
            for (int q = 0; q < 4; q++) {
                const uint32_t qoff = q * 1280 + koff;   // 16 rows * 80B
                uint32_t bh[4], bl[4];
                LDSM_X4(bh, sbase + boff_h + qoff);
                LDSM_X4(bl, sbase + boff_l + qoff);
                MMA_BF16(acc[2*q],   ah[0], ah[1], ah[2], ah[3], bh[0], bh[1]);
                MMA_BF16(acc[2*q],   ah[0], ah[1], ah[2], ah[3], bl[0], bl[1]);
                MMA_BF16(acc[2*q],   al[0], al[1], al[2], al[3], bh[0], bh[1]);
                MMA_BF16(acc[2*q+1], ah[0], ah[1], ah[2], ah[3], bh[2], bh[3]);
                MMA_BF16(acc[2*q+1], ah[0], ah[1], ah[2], ah[3], bl[2], bl[3]);
                MMA_BF16(acc[2*q+1], al[0], al[1], al[2], al[3], bh[2], bh[3]);
            }
        }
        __syncthreads();
    }

    // ---- epilogue: fused attention dots + fp16 h store ----
    const int ra = row0 + w * 16 + g;
    const float* ac = a_vec + hd * 2 * OUT_F;
    float s0 = 0.f, s1 = 0.f, t0 = 0.f, t1 = 0.f;
#pragma unroll
    for (int j = 0; j < 8; j++) {
        int c = j * 8 + 2 * tig;
        float2 as = *(const float2*)(ac + c);
        float2 an = *(const float2*)(ac + OUT_F + c);
        s0 += acc[j][0] * as.x + acc[j][1] * as.y;
        s1 += acc[j][2] * as.x + acc[j][3] * as.y;
        t0 += acc[j][0] * an.x + acc[j][1] * an.y;
        t1 += acc[j][2] * an.x + acc[j][3] * an.y;
    }
#pragma unroll
    for (int o = 1; o < 4; o <<= 1) {
        s0 += __shfl_xor_sync(0xffffffffu, s0, o);
        s1 += __shfl_xor_sync(0xffffffffu, s1, o);
        t0 += __shfl_xor_sync(0xffffffffu, t0, o);
        t1 += __shfl_xor_sync(0xffffffffu, t1, o);
    }
    if (tig == 0) {
        if (ra < N_NODES) {
            g_aself[ra * N_HEADS + hd]  = s0;
            g_aneigh[ra * N_HEADS + hd] = t0;
        }
        if (ra + 8 < N_NODES) {
            g_aself[(ra + 8) * N_HEADS + hd]  = s1;
            g_aneigh[(ra + 8) * N_HEADS + hd] = t1;
        }
    }
    if (ra < N_NODES) {
        __half2* hp = (__half2*)(g_hh + (size_t)ra * HF + hd * OUT_F);
#pragma unroll
        for (int j = 0; j < 8; j++)
            hp[j * 4 + tig] = __floats2half2_rn(acc[j][0], acc[j][1]);
    }
    if (ra + 8 < N_NODES) {
        __half2* hp = (__half2*)(g_hh + (size_t)(ra + 8) * HF + hd * OUT_F);
#pragma unroll
        for (int j = 0; j < 8; j++)
            hp[j * 4 + tig] = __floats2half2_rn(acc[j][2], acc[j][3]);
    }
}

// ---------------- aggregation: one warp per node, ALL 8 heads ----------------
__global__ void k_agg(float* __restrict__ out) {
    int wid = threadIdx.x >> 5, lane = threadIdx.x & 31;
    int n = blockIdx.x * 8 + wid;
    if (n >= N_NODES) return;

    int s = g_offs[n], e = g_offs[n + 1];
    const uint4* hh4 = (const uint4*)g_hh;          // 64 uint4 per node row
    const int vi = lane * 2;
    const int hsel = lane >> 2;
    const float an = __ldg(&g_aneigh[n * 8 + hsel]);

    float acc[16];
#pragma unroll
    for (int j = 0; j < 16; j++) acc[j] = 0.f;
    float den = 0.f;

    int u = 0; float m = 0.f;
    if (s < e) { u = __ldg(&g_csr_src[s]); m = __ldg(&g_csr_m[s]); }
    for (int i = s; i < e; i++) {
        int uc = u; float mc = m;
        if (i + 1 < e) { u = __ldg(&g_csr_src[i + 1]); m = __ldg(&g_csr_m[i + 1]); }
        float ev = __ldg(&g_aself[uc * 8 + hsel]) + an;
        ev = (ev > 0.f) ? ev : 0.2f * ev;           // leaky_relu
        float wgt = __expf(ev * mc);
        uint4 v0 = hh4[(size_t)uc * 64 + vi];
        uint4 v1 = hh4[(size_t)uc * 64 + vi + 1];
        den += wgt;
        const __half2* p0 = (const __half2*)&v0;
        const __half2* p1 = (const __half2*)&v1;
#pragma unroll
        for (int j = 0; j < 4; j++) {
            float2 f0 = __half22float2(p0[j]);
            float2 f1 = __half22float2(p1[j]);
            acc[2*j]     = fmaf(wgt, f0.x, acc[2*j]);
            acc[2*j+1]   = fmaf(wgt, f0.y, acc[2*j+1]);
            acc[8+2*j]   = fmaf(wgt, f1.x, acc[8+2*j]);
            acc[8+2*j+1] = fmaf(wgt, f1.y, acc[8+2*j+1]);
        }
    }
    float inv = 1.f / (den + 1e-16f);
    float* op = out + (size_t)n * HF + lane * 16;
#pragma unroll
    for (int j = 0; j < 16; j++) {
        float v = acc[j] * inv;
        acc[j] = (v > 0.f) ? v : expm1f(v);         // elu
    }
#pragma unroll
    for (int j = 0; j < 4; j++)
        *(float4*)(op + j * 4) = make_float4(acc[4*j], acc[4*j+1], acc[4*j+2], acc[4*j+3]);
}

// ---------------- launch: fork CSR chain onto a side stream ------------------
extern "C" void kernel_launch(void* const* d_in, const int* in_sizes, int n_in,
                              void* d_out, int out_size) {
    const float* x   = (const float*)d_in[0];
    const int*   src = (const int*)d_in[1];
    const int*   dst = (const int*)d_in[2];
    const float* M   = (const float*)d_in[3];
    const float* W   = (const float*)d_in[4];
    const float* a   = (const float*)d_in[5];
    float* out = (float*)d_out;

    static cudaStream_t s2 = nullptr;
    static cudaEvent_t ev_fork = nullptr, ev_join = nullptr;
    if (!s2) {
        cudaStreamCreateWithFlags(&s2, cudaStreamNonBlocking);
        cudaEventCreateWithFlags(&ev_fork, cudaEventDisableTiming);
        cudaEventCreateWithFlags(&ev_join, cudaEventDisableTiming);
        cudaFuncSetAttribute(k_gemm, cudaFuncAttributeMaxDynamicSharedMemorySize,
                             GEMM_SMEM);
    }

    // chain A (stream 0): prep -> gemm            (~150 us, tensor-bound)
    k_prep_x<<<(N_NODES * IN_F / 2 + 255) / 256, 256>>>(x);                 // 0
    k_prep_w<<<(N_HEADS * OUT_F * IN_F + 255) / 256, 256>>>(W);             // 1

    // fork chain B (stream s2): CSR build          (~42 us, atomics-bound)
    cudaEventRecord(ev_fork, 0);
    cudaStreamWaitEvent(s2, ev_fork, 0);
    k_zero_deg<<<(N_NODES + 255) / 256, 256, 0, s2>>>();                    // 2
    k_count<<<(N_EDGES + 255) / 256, 256, 0, s2>>>(dst);                    // 3
    k_scan<<<1, 1024, 0, s2>>>();                                           // 4

    k_gemm<<<dim3(N_HEADS, (N_NODES + 127) / 128), 256, GEMM_SMEM>>>(a);    // 5

    k_fill<<<(N_EDGES + 255) / 256, 256, 0, s2>>>(src, dst, M);             // 6

    // join, then aggregate
    cudaEventRecord(ev_join, s2);
    cudaStreamWaitEvent(0, ev_join, 0);
    k_agg<<<(N_NODES + 7) / 8, 256>>>(out);                                 // 7
}

// round 10
// speedup vs baseline: 2.7960x; 1.2173x over previous
#include <cuda_runtime.h>
#include <cuda_bf16.h>
#include <cuda_fp16.h>
#include <stdint.h>
#include <math.h>

#define N_NODES 50000
#define N_EDGES 800000
#define IN_F    256
#define OUT_F   64
#define N_HEADS 8
#define HF      (N_HEADS * OUT_F)   // 512

// ---------------- device scratch ---------------------------------------------
__device__ __half g_hh[(size_t)N_NODES * HF];      // fp16 h for gather (~51 MB)
__device__ float g_aself[N_NODES * N_HEADS];
__device__ float g_aneigh[N_NODES * N_HEADS];
__device__ int   g_deg[N_NODES];
__device__ int   g_offs[N_NODES + 1];
__device__ int   g_cursor[N_NODES];
__device__ int   g_csr_src[N_EDGES];
__device__ float g_csr_m[N_EDGES];
// fp16 operands
__device__ __half g_xh[(size_t)N_NODES * IN_F];
__device__ __half g_wth[N_HEADS * OUT_F * IN_F];   // [hd][n][k]

// ---------------- operand prep (fp32 -> fp16) --------------------------------
__global__ void k_prep_x(const float* __restrict__ x) {
    int i = blockIdx.x * blockDim.x + threadIdx.x;
    const int total = N_NODES * IN_F / 2;
    if (i < total) {
        float2 v = ((const float2*)x)[i];
        ((__half2*)g_xh)[i] = __floats2half2_rn(v.x, v.y);
    }
}

__global__ void k_prep_w(const float* __restrict__ W) {
    int i = blockIdx.x * blockDim.x + threadIdx.x;          // [hd][n][k] linear
    if (i < N_HEADS * OUT_F * IN_F) {
        int k  = i & (IN_F - 1);
        int n  = (i >> 8) & (OUT_F - 1);
        int hd = i >> 14;
        g_wth[i] = __float2half_rn(W[((size_t)hd * IN_F + k) * OUT_F + n]);
    }
}

// ---------------- CSR build --------------------------------------------------
__global__ void k_zero_deg() {
    int i = blockIdx.x * blockDim.x + threadIdx.x;
    if (i < N_NODES) g_deg[i] = 0;
}

__global__ void k_count(const int* __restrict__ dst) {
    int e = blockIdx.x * blockDim.x + threadIdx.x;
    if (e < N_EDGES) atomicAdd(&g_deg[dst[e]], 1);
}

__global__ void k_scan() {
    __shared__ int warp_sums[32];
    int tid = threadIdx.x, lane = tid & 31, wid = tid >> 5;
    int carry = 0;
    for (int base = 0; base < N_NODES; base += 1024) {
        int i = base + tid;
        int v = (i < N_NODES) ? g_deg[i] : 0;
        int xsum = v;
#pragma unroll
        for (int o = 1; o < 32; o <<= 1) {
            int t = __shfl_up_sync(0xffffffffu, xsum, o);
            if (lane >= o) xsum += t;
        }
        if (lane == 31) warp_sums[wid] = xsum;
        __syncthreads();
        if (wid == 0) {
            int s = warp_sums[lane];
#pragma unroll
            for (int o = 1; o < 32; o <<= 1) {
                int t = __shfl_up_sync(0xffffffffu, s, o);
                if (lane >= o) s += t;
            }
            warp_sums[lane] = s;
        }
        __syncthreads();
        int woff = (wid == 0) ? 0 : warp_sums[wid - 1];
        int incl = xsum + woff;
        if (i < N_NODES) {
            int excl = carry + incl - v;
            g_offs[i]   = excl;
            g_cursor[i] = excl;
        }
        carry += warp_sums[31];
        __syncthreads();
    }
    if (tid == 0) g_offs[N_NODES] = carry;
}

// fill CSR: (src, m) only — 8 B/edge scattered
__global__ void k_fill(const int* __restrict__ src, const int* __restrict__ dst,
                       const float* __restrict__ M) {
    int e = blockIdx.x * blockDim.x + threadIdx.x;
    if (e >= N_EDGES) return;
    int d = dst[e];
    int p = atomicAdd(&g_cursor[d], 1);
    g_csr_src[p] = src[e];
    g_csr_m[p]   = M[e];
}

// ---------------- fp16 mma.sync GEMM, cp.async double-buffered ---------------
#define MMA_F16(d, a0, a1, a2, a3, b0, b1)                                    \
    asm volatile(                                                             \
        "mma.sync.aligned.m16n8k16.row.col.f32.f16.f16.f32 "                  \
        "{%0,%1,%2,%3}, {%4,%5,%6,%7}, {%8,%9}, {%0,%1,%2,%3};"               \
        : "+f"(d[0]), "+f"(d[1]), "+f"(d[2]), "+f"(d[3])                      \
        : "r"(a0), "r"(a1), "r"(a2), "r"(a3), "r"(b0), "r"(b1))

#define LDSM_X4(r, addr)                                                      \
    asm volatile("ldmatrix.sync.aligned.m8n8.x4.shared.b16 {%0,%1,%2,%3}, [%4];" \
        : "=r"((r)[0]), "=r"((r)[1]), "=r"((r)[2]), "=r"((r)[3]) : "r"(addr))

#define CP16(dst, src, sz)                                                    \
    asm volatile("cp.async.cg.shared.global [%0], [%1], 16, %2;"              \
        :: "r"(dst), "l"(src), "r"(sz) : "memory")
#define CP_COMMIT() asm volatile("cp.async.commit_group;" ::: "memory")

// smem stage layout (bytes): rows padded to 20 words (80B)
#define OFF_A  0
#define OFF_B  10240
#define STAGE  15360
#define GEMM_SMEM (2 * STAGE)

__global__ void __launch_bounds__(256, 4) k_gemm(const float* __restrict__ a_vec) {
    extern __shared__ char smem[];
    const uint32_t sb = (uint32_t)__cvta_generic_to_shared(smem);

    const int tid  = threadIdx.x;
    const int w    = tid >> 5;
    const int lane = tid & 31;
    const int g    = lane >> 2;
    const int tig  = lane & 3;
    const int hd   = blockIdx.x;                 // head fastest: L2 x reuse
    const int row0 = blockIdx.y * 128;

    float acc[8][4];
#pragma unroll
    for (int j = 0; j < 8; j++)
#pragma unroll
        for (int i = 0; i < 4; i++) acc[j][i] = 0.f;

    // ldmatrix per-lane base offsets (within a stage)
    const int a_row  = w * 16 + (lane & 15);
    const int a_colw = (lane >> 4) * 4;
    const uint32_t aoff = OFF_A + (uint32_t)(a_row * 20 + a_colw) * 4;
    const int b_row  = (lane & 7) + ((lane >> 4) << 3);
    const int b_colw = ((lane >> 3) & 1) * 4;
    const uint32_t boff = OFF_B + (uint32_t)(b_row * 20 + b_colw) * 4;

    const uint4* x4 = (const uint4*)g_xh;        // 32 uint4 per x row
    const uint4* w4 = (const uint4*)g_wth;

    // per-thread cp.async assignments
    const int rA0 = tid >> 2,         qA0 = tid & 3;          // i = tid
    const int rA1 = (tid + 256) >> 2, qA1 = tid & 3;          // i = tid + 256
    const int gr0 = row0 + rA0, gr1 = row0 + rA1;
    const int szA0 = (gr0 < N_NODES) ? 16 : 0;
    const int szA1 = (gr1 < N_NODES) ? 16 : 0;
    const size_t sr0 = (size_t)((gr0 < N_NODES) ? gr0 : 0) * 32;
    const size_t sr1 = (size_t)((gr1 < N_NODES) ? gr1 : 0) * 32;
    const int rB = tid >> 2, qB = tid & 3;
    const size_t srB = (size_t)(hd * 64 + rB) * 32;
    const uint32_t dA0 = (uint32_t)(rA0 * 80 + qA0 * 16);
    const uint32_t dA1 = (uint32_t)(rA1 * 80 + qA1 * 16);
    const uint32_t dB  = (uint32_t)(rB * 80 + qB * 16);

#define ISSUE_TILE(st, kit)                                                   \
    do {                                                                      \
        const int kw = (kit) * 4;                                             \
        const uint32_t base = sb + (st) * STAGE;                              \
        CP16(base + OFF_A + dA0, x4 + sr0 + kw + qA0, szA0);                  \
        CP16(base + OFF_A + dA1, x4 + sr1 + kw + qA1, szA1);                  \
        CP16(base + OFF_B + dB,  w4 + srB + kw + qB, 16);                     \
        CP_COMMIT();                                                          \
    } while (0)

    ISSUE_TILE(0, 0);

    for (int kit = 0; kit < 8; kit++) {
        const int st = kit & 1;
        if (kit + 1 < 8) {
            ISSUE_TILE(st ^ 1, kit + 1);
            asm volatile("cp.async.wait_group 1;" ::: "memory");
        } else {
            asm volatile("cp.async.wait_group 0;" ::: "memory");
        }
        __syncthreads();

        const uint32_t sbase = st * STAGE + sb;
#pragma unroll
        for (int kt = 0; kt < 2; kt++) {
            const uint32_t koff = kt * 32;       // 8 words
            uint32_t ar[4];
            LDSM_X4(ar, sbase + aoff + koff);
#pragma unroll
            for (int q = 0; q < 4; q++) {
                const uint32_t qoff = q * 1280 + koff;   // 16 rows * 80B
                uint32_t br[4];
                LDSM_X4(br, sbase + boff + qoff);
                MMA_F16(acc[2*q],   ar[0], ar[1], ar[2], ar[3], br[0], br[1]);
                MMA_F16(acc[2*q+1], ar[0], ar[1], ar[2], ar[3], br[2], br[3]);
            }
        }
        __syncthreads();
    }

    // ---- epilogue: fused attention dots + fp16 h store ----
    const int ra = row0 + w * 16 + g;
    const float* ac = a_vec + hd * 2 * OUT_F;
    float s0 = 0.f, s1 = 0.f, t0 = 0.f, t1 = 0.f;
#pragma unroll
    for (int j = 0; j < 8; j++) {
        int c = j * 8 + 2 * tig;
        float2 as = *(const float2*)(ac + c);
        float2 an = *(const float2*)(ac + OUT_F + c);
        s0 += acc[j][0] * as.x + acc[j][1] * as.y;
        s1 += acc[j][2] * as.x + acc[j][3] * as.y;
        t0 += acc[j][0] * an.x + acc[j][1] * an.y;
        t1 += acc[j][2] * an.x + acc[j][3] * an.y;
    }
#pragma unroll
    for (int o = 1; o < 4; o <<= 1) {
        s0 += __shfl_xor_sync(0xffffffffu, s0, o);
        s1 += __shfl_xor_sync(0xffffffffu, s1, o);
        t0 += __shfl_xor_sync(0xffffffffu, t0, o);
        t1 += __shfl_xor_sync(0xffffffffu, t1, o);
    }
    if (tig == 0) {
        if (ra < N_NODES) {
            g_aself[ra * N_HEADS + hd]  = s0;
            g_aneigh[ra * N_HEADS + hd] = t0;
        }
        if (ra + 8 < N_NODES) {
            g_aself[(ra + 8) * N_HEADS + hd]  = s1;
            g_aneigh[(ra + 8) * N_HEADS + hd] = t1;
        }
    }
    if (ra < N_NODES) {
        __half2* hp = (__half2*)(g_hh + (size_t)ra * HF + hd * OUT_F);
#pragma unroll
        for (int j = 0; j < 8; j++)
            hp[j * 4 + tig] = __floats2half2_rn(acc[j][0], acc[j][1]);
    }
    if (ra + 8 < N_NODES) {
        __half2* hp = (__half2*)(g_hh + (size_t)(ra + 8) * HF + hd * OUT_F);
#pragma unroll
        for (int j = 0; j < 8; j++)
            hp[j * 4 + tig] = __floats2half2_rn(acc[j][2], acc[j][3]);
    }
}

// ---------------- aggregation: one warp per node, ALL 8 heads ----------------
__global__ void k_agg(float* __restrict__ out) {
    int wid = threadIdx.x >> 5, lane = threadIdx.x & 31;
    int n = blockIdx.x * 8 + wid;
    if (n >= N_NODES) return;

    int s = g_offs[n], e = g_offs[n + 1];
    const uint4* hh4 = (const uint4*)g_hh;          // 64 uint4 per node row
    const int vi = lane * 2;
    const int hsel = lane >> 2;
    const float an = __ldg(&g_aneigh[n * 8 + hsel]);

    float acc[16];
#pragma unroll
    for (int j = 0; j < 16; j++) acc[j] = 0.f;
    float den = 0.f;

    int u = 0; float m = 0.f;
    if (s < e) { u = __ldg(&g_csr_src[s]); m = __ldg(&g_csr_m[s]); }
    for (int i = s; i < e; i++) {
        int uc = u; float mc = m;
        if (i + 1 < e) { u = __ldg(&g_csr_src[i + 1]); m = __ldg(&g_csr_m[i + 1]); }
        float ev = __ldg(&g_aself[uc * 8 + hsel]) + an;
        ev = (ev > 0.f) ? ev : 0.2f * ev;           // leaky_relu
        float wgt = __expf(ev * mc);
        uint4 v0 = hh4[(size_t)uc * 64 + vi];
        uint4 v1 = hh4[(size_t)uc * 64 + vi + 1];
        den += wgt;
        const __half2* p0 = (const __half2*)&v0;
        const __half2* p1 = (const __half2*)&v1;
#pragma unroll
        for (int j = 0; j < 4; j++) {
            float2 f0 = __half22float2(p0[j]);
            float2 f1 = __half22float2(p1[j]);
            acc[2*j]     = fmaf(wgt, f0.x, acc[2*j]);
            acc[2*j+1]   = fmaf(wgt, f0.y, acc[2*j+1]);
            acc[8+2*j]   = fmaf(wgt, f1.x, acc[8+2*j]);
            acc[8+2*j+1] = fmaf(wgt, f1.y, acc[8+2*j+1]);
        }
    }
    float inv = 1.f / (den + 1e-16f);
    float* op = out + (size_t)n * HF + lane * 16;
#pragma unroll
    for (int j = 0; j < 16; j++) {
        float v = acc[j] * inv;
        acc[j] = (v > 0.f) ? v : expm1f(v);         // elu
    }
#pragma unroll
    for (int j = 0; j < 4; j++)
        *(float4*)(op + j * 4) = make_float4(acc[4*j], acc[4*j+1], acc[4*j+2], acc[4*j+3]);
}

// ---------------- launch: fork CSR chain onto a side stream ------------------
extern "C" void kernel_launch(void* const* d_in, const int* in_sizes, int n_in,
                              void* d_out, int out_size) {
    const float* x   = (const float*)d_in[0];
    const int*   src = (const int*)d_in[1];
    const int*   dst = (const int*)d_in[2];
    const float* M   = (const float*)d_in[3];
    const float* W   = (const float*)d_in[4];
    const float* a   = (const float*)d_in[5];
    float* out = (float*)d_out;

    static cudaStream_t s2 = nullptr;
    static cudaEvent_t ev_fork = nullptr, ev_join = nullptr;
    if (!s2) {
        cudaStreamCreateWithFlags(&s2, cudaStreamNonBlocking);
        cudaEventCreateWithFlags(&ev_fork, cudaEventDisableTiming);
        cudaEventCreateWithFlags(&ev_join, cudaEventDisableTiming);
        cudaFuncSetAttribute(k_gemm, cudaFuncAttributeMaxDynamicSharedMemorySize,
                             GEMM_SMEM);
    }

    // chain A (stream 0): prep -> gemm
    k_prep_x<<<(N_NODES * IN_F / 2 + 255) / 256, 256>>>(x);                 // 0
    k_prep_w<<<(N_HEADS * OUT_F * IN_F + 255) / 256, 256>>>(W);             // 1

    // fork chain B (stream s2): CSR build
    cudaEventRecord(ev_fork, 0);
    cudaStreamWaitEvent(s2, ev_fork, 0);
    k_zero_deg<<<(N_NODES + 255) / 256, 256, 0, s2>>>();                    // 2
    k_count<<<(N_EDGES + 255) / 256, 256, 0, s2>>>(dst);                    // 3
    k_scan<<<1, 1024, 0, s2>>>();                                           // 4

    k_gemm<<<dim3(N_HEADS, (N_NODES + 127) / 128), 256, GEMM_SMEM>>>(a);    // 5

    k_fill<<<(N_EDGES + 255) / 256, 256, 0, s2>>>(src, dst, M);             // 6

    // join, then aggregate
    cudaEventRecord(ev_join, s2);
    cudaStreamWaitEvent(0, ev_join, 0);
    k_agg<<<(N_NODES + 7) / 8, 256>>>(out);                                 // 7
}

// round 11
// speedup vs baseline: 2.9173x; 1.0434x over previous
#include <cuda_runtime.h>
#include <cuda_bf16.h>
#include <cuda_fp16.h>
#include <stdint.h>
#include <math.h>

#define N_NODES 50000
#define N_EDGES 800000
#define IN_F    256
#define OUT_F   64
#define N_HEADS 8
#define HF      (N_HEADS * OUT_F)   // 512

// ---------------- device scratch ---------------------------------------------
__device__ __half g_hh[(size_t)N_NODES * HF];      // fp16 h for gather (~51 MB)
__device__ float g_aself[N_NODES * N_HEADS];
__device__ float g_aneigh[N_NODES * N_HEADS];
__device__ int   g_deg[N_NODES];
__device__ int   g_offs[N_NODES + 1];
__device__ int   g_cursor[N_NODES];
__device__ int   g_csr_src[N_EDGES];
__device__ float g_csr_m[N_EDGES];
// fp16 operands
__device__ __half g_xh[(size_t)N_NODES * IN_F];
__device__ __half g_wth[N_HEADS * OUT_F * IN_F];   // [hd][n][k]

// ---------------- operand prep (fp32 -> fp16) --------------------------------
__global__ void k_prep_x(const float* __restrict__ x) {
    int i = blockIdx.x * blockDim.x + threadIdx.x;
    const int total = N_NODES * IN_F / 2;
    if (i < total) {
        float2 v = ((const float2*)x)[i];
        ((__half2*)g_xh)[i] = __floats2half2_rn(v.x, v.y);
    }
}

__global__ void k_prep_w(const float* __restrict__ W) {
    int i = blockIdx.x * blockDim.x + threadIdx.x;          // [hd][n][k] linear
    if (i < N_HEADS * OUT_F * IN_F) {
        int k  = i & (IN_F - 1);
        int n  = (i >> 8) & (OUT_F - 1);
        int hd = i >> 14;
        g_wth[i] = __float2half_rn(W[((size_t)hd * IN_F + k) * OUT_F + n]);
    }
}

// ---------------- CSR build --------------------------------------------------
__global__ void k_zero_deg() {
    int i = blockIdx.x * blockDim.x + threadIdx.x;
    if (i < N_NODES) g_deg[i] = 0;
}

__global__ void k_count(const int* __restrict__ dst) {
    int e = blockIdx.x * blockDim.x + threadIdx.x;
    if (e < N_EDGES) atomicAdd(&g_deg[dst[e]], 1);
}

__global__ void k_scan() {
    __shared__ int warp_sums[32];
    int tid = threadIdx.x, lane = tid & 31, wid = tid >> 5;
    int carry = 0;
    for (int base = 0; base < N_NODES; base += 1024) {
        int i = base + tid;
        int v = (i < N_NODES) ? g_deg[i] : 0;
        int xsum = v;
#pragma unroll
        for (int o = 1; o < 32; o <<= 1) {
            int t = __shfl_up_sync(0xffffffffu, xsum, o);
            if (lane >= o) xsum += t;
        }
        if (lane == 31) warp_sums[wid] = xsum;
        __syncthreads();
        if (wid == 0) {
            int s = warp_sums[lane];
#pragma unroll
            for (int o = 1; o < 32; o <<= 1) {
                int t = __shfl_up_sync(0xffffffffu, s, o);
                if (lane >= o) s += t;
            }
            warp_sums[lane] = s;
        }
        __syncthreads();
        int woff = (wid == 0) ? 0 : warp_sums[wid - 1];
        int incl = xsum + woff;
        if (i < N_NODES) {
            int excl = carry + incl - v;
            g_offs[i]   = excl;
            g_cursor[i] = excl;
        }
        carry += warp_sums[31];
        __syncthreads();
    }
    if (tid == 0) g_offs[N_NODES] = carry;
}

// fill CSR: (src, m) only — 8 B/edge scattered
__global__ void k_fill(const int* __restrict__ src, const int* __restrict__ dst,
                       const float* __restrict__ M) {
    int e = blockIdx.x * blockDim.x + threadIdx.x;
    if (e >= N_EDGES) return;
    int d = dst[e];
    int p = atomicAdd(&g_cursor[d], 1);
    g_csr_src[p] = src[e];
    g_csr_m[p]   = M[e];
}

// ---------------- fp16 mma.sync GEMM, BM=256, cp.async double-buffered -------
#define MMA_F16(d, a0, a1, a2, a3, b0, b1)                                    \
    asm volatile(                                                             \
        "mma.sync.aligned.m16n8k16.row.col.f32.f16.f16.f32 "                  \
        "{%0,%1,%2,%3}, {%4,%5,%6,%7}, {%8,%9}, {%0,%1,%2,%3};"               \
        : "+f"(d[0]), "+f"(d[1]), "+f"(d[2]), "+f"(d[3])                      \
        : "r"(a0), "r"(a1), "r"(a2), "r"(a3), "r"(b0), "r"(b1))

#define LDSM_X4(r, addr)                                                      \
    asm volatile("ldmatrix.sync.aligned.m8n8.x4.shared.b16 {%0,%1,%2,%3}, [%4];" \
        : "=r"((r)[0]), "=r"((r)[1]), "=r"((r)[2]), "=r"((r)[3]) : "r"(addr))

#define CP16(dst, src, sz)                                                    \
    asm volatile("cp.async.cg.shared.global [%0], [%1], 16, %2;"              \
        :: "r"(dst), "l"(src), "r"(sz) : "memory")
#define CP_COMMIT() asm volatile("cp.async.commit_group;" ::: "memory")

// smem stage layout (bytes): rows padded to 20 words (80B)
#define OFF_A  0
#define OFF_B  20480          // 256 rows * 80B
#define STAGE  25600          // + 64 rows * 80B
#define GEMM_SMEM (2 * STAGE)
#define BM 256

__global__ void __launch_bounds__(256, 2) k_gemm(const float* __restrict__ a_vec) {
    extern __shared__ char smem[];
    const uint32_t sb = (uint32_t)__cvta_generic_to_shared(smem);

    const int tid  = threadIdx.x;
    const int w    = tid >> 5;
    const int lane = tid & 31;
    const int g    = lane >> 2;
    const int tig  = lane & 3;
    const int hd   = blockIdx.x;                 // head fastest: L2 x reuse
    const int row0 = blockIdx.y * BM;

    float acc0[8][4], acc1[8][4];
#pragma unroll
    for (int j = 0; j < 8; j++)
#pragma unroll
        for (int i = 0; i < 4; i++) { acc0[j][i] = 0.f; acc1[j][i] = 0.f; }

    // ldmatrix per-lane base offsets (within a stage): warp covers rows w*32..w*32+31
    const int a_row  = w * 32 + (lane & 15);
    const int a_colw = (lane >> 4) * 4;
    const uint32_t aoff0 = OFF_A + (uint32_t)(a_row * 20 + a_colw) * 4;
    const uint32_t aoff1 = aoff0 + 16 * 80;      // +16 rows
    const int b_row  = (lane & 7) + ((lane >> 4) << 3);
    const int b_colw = ((lane >> 3) & 1) * 4;
    const uint32_t boff = OFF_B + (uint32_t)(b_row * 20 + b_colw) * 4;

    const uint4* x4 = (const uint4*)g_xh;        // 32 uint4 per x row
    const uint4* w4 = (const uint4*)g_wth;

    // per-thread cp.async assignments: A gets 4 uint4/thread, B 1/thread
    int   rA[4], szA[4];
    size_t srA[4];
    uint32_t dA[4];
    const int qA = tid & 3;
#pragma unroll
    for (int t = 0; t < 4; t++) {
        int i = tid + t * 256;
        rA[t] = i >> 2;
        int gr = row0 + rA[t];
        szA[t] = (gr < N_NODES) ? 16 : 0;
        srA[t] = (size_t)((gr < N_NODES) ? gr : 0) * 32;
        dA[t]  = (uint32_t)(rA[t] * 80 + qA * 16);
    }
    const int rB = tid >> 2, qB = tid & 3;
    const size_t srB = (size_t)(hd * 64 + rB) * 32;
    const uint32_t dB = (uint32_t)(rB * 80 + qB * 16);

#define ISSUE_TILE(st, kit)                                                   \
    do {                                                                      \
        const int kw = (kit) * 4;                                             \
        const uint32_t base = sb + (st) * STAGE;                              \
        CP16(base + OFF_A + dA[0], x4 + srA[0] + kw + qA, szA[0]);            \
        CP16(base + OFF_A + dA[1], x4 + srA[1] + kw + qA, szA[1]);            \
        CP16(base + OFF_A + dA[2], x4 + srA[2] + kw + qA, szA[2]);            \
        CP16(base + OFF_A + dA[3], x4 + srA[3] + kw + qA, szA[3]);            \
        CP16(base + OFF_B + dB,  w4 + srB + kw + qB, 16);                     \
        CP_COMMIT();                                                          \
    } while (0)

    ISSUE_TILE(0, 0);

    for (int kit = 0; kit < 8; kit++) {
        const int st = kit & 1;
        if (kit + 1 < 8) {
            ISSUE_TILE(st ^ 1, kit + 1);
            asm volatile("cp.async.wait_group 1;" ::: "memory");
        } else {
            asm volatile("cp.async.wait_group 0;" ::: "memory");
        }
        __syncthreads();

        const uint32_t sbase = st * STAGE + sb;
#pragma unroll
        for (int kt = 0; kt < 2; kt++) {
            const uint32_t koff = kt * 32;       // 8 words
            uint32_t ar0[4], ar1[4];
            LDSM_X4(ar0, sbase + aoff0 + koff);
            LDSM_X4(ar1, sbase + aoff1 + koff);
#pragma unroll
            for (int q = 0; q < 4; q++) {
                const uint32_t qoff = q * 1280 + koff;   // 16 rows * 80B
                uint32_t br[4];
                LDSM_X4(br, sbase + boff + qoff);
                MMA_F16(acc0[2*q],   ar0[0], ar0[1], ar0[2], ar0[3], br[0], br[1]);
                MMA_F16(acc0[2*q+1], ar0[0], ar0[1], ar0[2], ar0[3], br[2], br[3]);
                MMA_F16(acc1[2*q],   ar1[0], ar1[1], ar1[2], ar1[3], br[0], br[1]);
                MMA_F16(acc1[2*q+1], ar1[0], ar1[1], ar1[2], ar1[3], br[2], br[3]);
            }
        }
        __syncthreads();
    }

    // ---- epilogue: fused attention dots + fp16 h store (two m16 blocks) ----
    const float* ac = a_vec + hd * 2 * OUT_F;
#pragma unroll
    for (int half = 0; half < 2; half++) {
        float (*acc)[4] = half ? acc1 : acc0;
        const int ra = row0 + w * 32 + half * 16 + g;
        float s0 = 0.f, s1 = 0.f, t0 = 0.f, t1 = 0.f;
#pragma unroll
        for (int j = 0; j < 8; j++) {
            int c = j * 8 + 2 * tig;
            float2 as = *(const float2*)(ac + c);
            float2 an = *(const float2*)(ac + OUT_F + c);
            s0 += acc[j][0] * as.x + acc[j][1] * as.y;
            s1 += acc[j][2] * as.x + acc[j][3] * as.y;
            t0 += acc[j][0] * an.x + acc[j][1] * an.y;
            t1 += acc[j][2] * an.x + acc[j][3] * an.y;
        }
#pragma unroll
        for (int o = 1; o < 4; o <<= 1) {
            s0 += __shfl_xor_sync(0xffffffffu, s0, o);
            s1 += __shfl_xor_sync(0xffffffffu, s1, o);
            t0 += __shfl_xor_sync(0xffffffffu, t0, o);
            t1 += __shfl_xor_sync(0xffffffffu, t1, o);
        }
        if (tig == 0) {
            if (ra < N_NODES) {
                g_aself[ra * N_HEADS + hd]  = s0;
                g_aneigh[ra * N_HEADS + hd] = t0;
            }
            if (ra + 8 < N_NODES) {
                g_aself[(ra + 8) * N_HEADS + hd]  = s1;
                g_aneigh[(ra + 8) * N_HEADS + hd] = t1;
            }
        }
        if (ra < N_NODES) {
            __half2* hp = (__half2*)(g_hh + (size_t)ra * HF + hd * OUT_F);
#pragma unroll
            for (int j = 0; j < 8; j++)
                hp[j * 4 + tig] = __floats2half2_rn(acc[j][0], acc[j][1]);
        }
        if (ra + 8 < N_NODES) {
            __half2* hp = (__half2*)(g_hh + (size_t)(ra + 8) * HF + hd * OUT_F);
#pragma unroll
            for (int j = 0; j < 8; j++)
                hp[j * 4 + tig] = __floats2half2_rn(acc[j][2], acc[j][3]);
        }
    }
}

// ---------------- aggregation: one warp per node, ALL 8 heads ----------------
__global__ void k_agg(float* __restrict__ out) {
    int wid = threadIdx.x >> 5, lane = threadIdx.x & 31;
    int n = blockIdx.x * 8 + wid;
    if (n >= N_NODES) return;

    int s = g_offs[n], e = g_offs[n + 1];
    const uint4* hh4 = (const uint4*)g_hh;          // 64 uint4 per node row
    const int vi = lane * 2;
    const int hsel = lane >> 2;
    const float an = __ldg(&g_aneigh[n * 8 + hsel]);

    float acc[16];
#pragma unroll
    for (int j = 0; j < 16; j++) acc[j] = 0.f;
    float den = 0.f;

    int u = 0; float m = 0.f;
    if (s < e) { u = __ldg(&g_csr_src[s]); m = __ldg(&g_csr_m[s]); }
    for (int i = s; i < e; i++) {
        int uc = u; float mc = m;
        if (i + 1 < e) { u = __ldg(&g_csr_src[i + 1]); m = __ldg(&g_csr_m[i + 1]); }
        float ev = __ldg(&g_aself[uc * 8 + hsel]) + an;
        ev = (ev > 0.f) ? ev : 0.2f * ev;           // leaky_relu
        float wgt = __expf(ev * mc);
        uint4 v0 = hh4[(size_t)uc * 64 + vi];
        uint4 v1 = hh4[(size_t)uc * 64 + vi + 1];
        den += wgt;
        const __half2* p0 = (const __half2*)&v0;
        const __half2* p1 = (const __half2*)&v1;
#pragma unroll
        for (int j = 0; j < 4; j++) {
            float2 f0 = __half22float2(p0[j]);
            float2 f1 = __half22float2(p1[j]);
            acc[2*j]     = fmaf(wgt, f0.x, acc[2*j]);
            acc[2*j+1]   = fmaf(wgt, f0.y, acc[2*j+1]);
            acc[8+2*j]   = fmaf(wgt, f1.x, acc[8+2*j]);
            acc[8+2*j+1] = fmaf(wgt, f1.y, acc[8+2*j+1]);
        }
    }
    float inv = 1.f / (den + 1e-16f);
    float* op = out + (size_t)n * HF + lane * 16;
#pragma unroll
    for (int j = 0; j < 16; j++) {
        float v = acc[j] * inv;
        acc[j] = (v > 0.f) ? v : expm1f(v);         // elu
    }
#pragma unroll
    for (int j = 0; j < 4; j++)
        *(float4*)(op + j * 4) = make_float4(acc[4*j], acc[4*j+1], acc[4*j+2], acc[4*j+3]);
}

// ---------------- launch: fork CSR chain onto a side stream ------------------
extern "C" void kernel_launch(void* const* d_in, const int* in_sizes, int n_in,
                              void* d_out, int out_size) {
    const float* x   = (const float*)d_in[0];
    const int*   src = (const int*)d_in[1];
    const int*   dst = (const int*)d_in[2];
    const float* M   = (const float*)d_in[3];
    const float* W   = (const float*)d_in[4];
    const float* a   = (const float*)d_in[5];
    float* out = (float*)d_out;

    static cudaStream_t s2 = nullptr;
    static cudaEvent_t ev_fork = nullptr, ev_join = nullptr;
    if (!s2) {
        cudaStreamCreateWithFlags(&s2, cudaStreamNonBlocking);
        cudaEventCreateWithFlags(&ev_fork, cudaEventDisableTiming);
        cudaEventCreateWithFlags(&ev_join, cudaEventDisableTiming);
        cudaFuncSetAttribute(k_gemm, cudaFuncAttributeMaxDynamicSharedMemorySize,
                             GEMM_SMEM);
    }

    // chain A (stream 0): prep -> gemm
    k_prep_x<<<(N_NODES * IN_F / 2 + 255) / 256, 256>>>(x);                 // 0
    k_prep_w<<<(N_HEADS * OUT_F * IN_F + 255) / 256, 256>>>(W);             // 1

    // fork chain B (stream s2): CSR build
    cudaEventRecord(ev_fork, 0);
    cudaStreamWaitEvent(s2, ev_fork, 0);
    k_zero_deg<<<(N_NODES + 255) / 256, 256, 0, s2>>>();                    // 2
    k_count<<<(N_EDGES + 255) / 256, 256, 0, s2>>>(dst);                    // 3
    k_scan<<<1, 1024, 0, s2>>>();                                           // 4

    k_gemm<<<dim3(N_HEADS, (N_NODES + BM - 1) / BM), 256, GEMM_SMEM>>>(a);  // 5

    k_fill<<<(N_EDGES + 255) / 256, 256, 0, s2>>>(src, dst, M);             // 6

    // join, then aggregate
    cudaEventRecord(ev_join, s2);
    cudaStreamWaitEvent(0, ev_join, 0);
    k_agg<<<(N_NODES + 7) / 8, 256>>>(out);                                 // 7
}

// round 12
// speedup vs baseline: 3.1836x; 1.0913x over previous
#include <cuda_runtime.h>
#include <cuda_bf16.h>
#include <cuda_fp16.h>
#include <stdint.h>
#include <math.h>

#define N_NODES 50000
#define N_EDGES 800000
#define IN_F    256
#define OUT_F   64
#define N_HEADS 8
#define HF      (N_HEADS * OUT_F)   // 512

// ---------------- device scratch ---------------------------------------------
__device__ __half g_hh[(size_t)N_NODES * HF];      // fp16 h for gather (~51 MB)
__device__ float g_aself[N_NODES * N_HEADS];
__device__ float g_aneigh[N_NODES * N_HEADS];
__device__ int   g_deg[N_NODES];
__device__ int   g_offs[N_NODES + 1];
__device__ int   g_cursor[N_NODES];
__device__ int   g_csr_src[N_EDGES];
__device__ float g_csr_m[N_EDGES];
// fp16 operands
__device__ __half g_xh[(size_t)N_NODES * IN_F];
__device__ __half g_wth[N_HEADS * OUT_F * IN_F];   // [hd][n][k]

// ---------------- operand prep (fp32 -> fp16), x and W merged ----------------
#define XPAIRS (N_NODES * IN_F / 2)
#define WELEMS (N_HEADS * OUT_F * IN_F)
__global__ void k_prep(const float* __restrict__ x, const float* __restrict__ W) {
    int i = blockIdx.x * blockDim.x + threadIdx.x;
    if (i < XPAIRS) {
        float2 v = ((const float2*)x)[i];
        ((__half2*)g_xh)[i] = __floats2half2_rn(v.x, v.y);
    } else {
        int j = i - XPAIRS;
        if (j < WELEMS) {
            int k  = j & (IN_F - 1);
            int n  = (j >> 8) & (OUT_F - 1);
            int hd = j >> 14;
            g_wth[j] = __float2half_rn(W[((size_t)hd * IN_F + k) * OUT_F + n]);
        }
    }
}

// ---------------- CSR build --------------------------------------------------
__global__ void k_zero_deg() {
    int i = blockIdx.x * blockDim.x + threadIdx.x;
    if (i < N_NODES) g_deg[i] = 0;
}

__global__ void k_count(const int* __restrict__ dst) {
    int e = blockIdx.x * blockDim.x + threadIdx.x;
    if (e < N_EDGES) atomicAdd(&g_deg[dst[e]], 1);
}

__global__ void k_scan() {
    __shared__ int warp_sums[32];
    int tid = threadIdx.x, lane = tid & 31, wid = tid >> 5;
    int carry = 0;
    for (int base = 0; base < N_NODES; base += 1024) {
        int i = base + tid;
        int v = (i < N_NODES) ? g_deg[i] : 0;
        int xsum = v;
#pragma unroll
        for (int o = 1; o < 32; o <<= 1) {
            int t = __shfl_up_sync(0xffffffffu, xsum, o);
            if (lane >= o) xsum += t;
        }
        if (lane == 31) warp_sums[wid] = xsum;
        __syncthreads();
        if (wid == 0) {
            int s = warp_sums[lane];
#pragma unroll
            for (int o = 1; o < 32; o <<= 1) {
                int t = __shfl_up_sync(0xffffffffu, s, o);
                if (lane >= o) s += t;
            }
            warp_sums[lane] = s;
        }
        __syncthreads();
        int woff = (wid == 0) ? 0 : warp_sums[wid - 1];
        int incl = xsum + woff;
        if (i < N_NODES) {
            int excl = carry + incl - v;
            g_offs[i]   = excl;
            g_cursor[i] = excl;
        }
        carry += warp_sums[31];
        __syncthreads();
    }
    if (tid == 0) g_offs[N_NODES] = carry;
}

// fill CSR: (src, m) only — 8 B/edge scattered
__global__ void k_fill(const int* __restrict__ src, const int* __restrict__ dst,
                       const float* __restrict__ M) {
    int e = blockIdx.x * blockDim.x + threadIdx.x;
    if (e >= N_EDGES) return;
    int d = dst[e];
    int p = atomicAdd(&g_cursor[d], 1);
    g_csr_src[p] = src[e];
    g_csr_m[p]   = M[e];
}

// ---------------- fp16 mma.sync GEMM, BM=256, cp.async 3-stage ---------------
#define MMA_F16(d, a0, a1, a2, a3, b0, b1)                                    \
    asm volatile(                                                             \
        "mma.sync.aligned.m16n8k16.row.col.f32.f16.f16.f32 "                  \
        "{%0,%1,%2,%3}, {%4,%5,%6,%7}, {%8,%9}, {%0,%1,%2,%3};"               \
        : "+f"(d[0]), "+f"(d[1]), "+f"(d[2]), "+f"(d[3])                      \
        : "r"(a0), "r"(a1), "r"(a2), "r"(a3), "r"(b0), "r"(b1))

#define LDSM_X4(r, addr)                                                      \
    asm volatile("ldmatrix.sync.aligned.m8n8.x4.shared.b16 {%0,%1,%2,%3}, [%4];" \
        : "=r"((r)[0]), "=r"((r)[1]), "=r"((r)[2]), "=r"((r)[3]) : "r"(addr))

#define CP16(dst, src, sz)                                                    \
    asm volatile("cp.async.cg.shared.global [%0], [%1], 16, %2;"              \
        :: "r"(dst), "l"(src), "r"(sz) : "memory")
#define CP_COMMIT() asm volatile("cp.async.commit_group;" ::: "memory")

// smem stage layout (bytes): rows padded to 20 words (80B)
#define OFF_A  0
#define OFF_B  20480          // 256 rows * 80B
#define STAGE  25600          // + 64 rows * 80B
#define GEMM_SMEM (3 * STAGE) // 76800
#define BM 256

__global__ void __launch_bounds__(256, 2) k_gemm(const float* __restrict__ a_vec) {
    extern __shared__ char smem[];
    const uint32_t sb = (uint32_t)__cvta_generic_to_shared(smem);

    const int tid  = threadIdx.x;
    const int w    = tid >> 5;
    const int lane = tid & 31;
    const int g    = lane >> 2;
    const int tig  = lane & 3;
    const int hd   = blockIdx.x;                 // head fastest: L2 x reuse
    const int row0 = blockIdx.y * BM;

    float acc0[8][4], acc1[8][4];
#pragma unroll
    for (int j = 0; j < 8; j++)
#pragma unroll
        for (int i = 0; i < 4; i++) { acc0[j][i] = 0.f; acc1[j][i] = 0.f; }

    // ldmatrix per-lane base offsets (within a stage): warp covers rows w*32..w*32+31
    const int a_row  = w * 32 + (lane & 15);
    const int a_colw = (lane >> 4) * 4;
    const uint32_t aoff0 = OFF_A + (uint32_t)(a_row * 20 + a_colw) * 4;
    const uint32_t aoff1 = aoff0 + 16 * 80;      // +16 rows
    const int b_row  = (lane & 7) + ((lane >> 4) << 3);
    const int b_colw = ((lane >> 3) & 1) * 4;
    const uint32_t boff = OFF_B + (uint32_t)(b_row * 20 + b_colw) * 4;

    const uint4* x4 = (const uint4*)g_xh;        // 32 uint4 per x row
    const uint4* w4 = (const uint4*)g_wth;

    // per-thread cp.async assignments: A gets 4 uint4/thread, B 1/thread
    int   rA[4], szA[4];
    size_t srA[4];
    uint32_t dA[4];
    const int qA = tid & 3;
#pragma unroll
    for (int t = 0; t < 4; t++) {
        int i = tid + t * 256;
        rA[t] = i >> 2;
        int gr = row0 + rA[t];
        szA[t] = (gr < N_NODES) ? 16 : 0;
        srA[t] = (size_t)((gr < N_NODES) ? gr : 0) * 32;
        dA[t]  = (uint32_t)(rA[t] * 80 + qA * 16);
    }
    const int rB = tid >> 2, qB = tid & 3;
    const size_t srB = (size_t)(hd * 64 + rB) * 32;
    const uint32_t dB = (uint32_t)(rB * 80 + qB * 16);

#define ISSUE_TILE(st, kit)                                                   \
    do {                                                                      \
        const int kw = (kit) * 4;                                             \
        const uint32_t base = sb + (st) * STAGE;                              \
        CP16(base + OFF_A + dA[0], x4 + srA[0] + kw + qA, szA[0]);            \
        CP16(base + OFF_A + dA[1], x4 + srA[1] + kw + qA, szA[1]);            \
        CP16(base + OFF_A + dA[2], x4 + srA[2] + kw + qA, szA[2]);            \
        CP16(base + OFF_A + dA[3], x4 + srA[3] + kw + qA, szA[3]);            \
        CP16(base + OFF_B + dB,  w4 + srB + kw + qB, 16);                     \
        CP_COMMIT();                                                          \
    } while (0)

    ISSUE_TILE(0, 0);
    ISSUE_TILE(1, 1);

#pragma unroll
    for (int kit = 0; kit < 8; kit++) {
        const int st = kit % 3;
        if (kit + 2 < 8) {
            ISSUE_TILE((kit + 2) % 3, kit + 2);
            asm volatile("cp.async.wait_group 2;" ::: "memory");
        } else if (kit + 1 < 8) {
            asm volatile("cp.async.wait_group 1;" ::: "memory");
        } else {
            asm volatile("cp.async.wait_group 0;" ::: "memory");
        }
        __syncthreads();

        const uint32_t sbase = st * STAGE + sb;
#pragma unroll
        for (int kt = 0; kt < 2; kt++) {
            const uint32_t koff = kt * 32;       // 8 words
            uint32_t ar0[4], ar1[4];
            LDSM_X4(ar0, sbase + aoff0 + koff);
            LDSM_X4(ar1, sbase + aoff1 + koff);
#pragma unroll
            for (int q = 0; q < 4; q++) {
                const uint32_t qoff = q * 1280 + koff;   // 16 rows * 80B
                uint32_t br[4];
                LDSM_X4(br, sbase + boff + qoff);
                MMA_F16(acc0[2*q],   ar0[0], ar0[1], ar0[2], ar0[3], br[0], br[1]);
                MMA_F16(acc0[2*q+1], ar0[0], ar0[1], ar0[2], ar0[3], br[2], br[3]);
                MMA_F16(acc1[2*q],   ar1[0], ar1[1], ar1[2], ar1[3], br[0], br[1]);
                MMA_F16(acc1[2*q+1], ar1[0], ar1[1], ar1[2], ar1[3], br[2], br[3]);
            }
        }
        __syncthreads();
    }

    // ---- epilogue: fused attention dots + fp16 h store (two m16 blocks) ----
    const float* ac = a_vec + hd * 2 * OUT_F;
#pragma unroll
    for (int half = 0; half < 2; half++) {
        float (*acc)[4] = half ? acc1 : acc0;
        const int ra = row0 + w * 32 + half * 16 + g;
        float s0 = 0.f, s1 = 0.f, t0 = 0.f, t1 = 0.f;
#pragma unroll
        for (int j = 0; j < 8; j++) {
            int c = j * 8 + 2 * tig;
            float2 as = *(const float2*)(ac + c);
            float2 an = *(const float2*)(ac + OUT_F + c);
            s0 += acc[j][0] * as.x + acc[j][1] * as.y;
            s1 += acc[j][2] * as.x + acc[j][3] * as.y;
            t0 += acc[j][0] * an.x + acc[j][1] * an.y;
            t1 += acc[j][2] * an.x + acc[j][3] * an.y;
        }
#pragma unroll
        for (int o = 1; o < 4; o <<= 1) {
            s0 += __shfl_xor_sync(0xffffffffu, s0, o);
            s1 += __shfl_xor_sync(0xffffffffu, s1, o);
            t0 += __shfl_xor_sync(0xffffffffu, t0, o);
            t1 += __shfl_xor_sync(0xffffffffu, t1, o);
        }
        if (tig == 0) {
            if (ra < N_NODES) {
                g_aself[ra * N_HEADS + hd]  = s0;
                g_aneigh[ra * N_HEADS + hd] = t0;
            }
            if (ra + 8 < N_NODES) {
                g_aself[(ra + 8) * N_HEADS + hd]  = s1;
                g_aneigh[(ra + 8) * N_HEADS + hd] = t1;
            }
        }
        if (ra < N_NODES) {
            __half2* hp = (__half2*)(g_hh + (size_t)ra * HF + hd * OUT_F);
#pragma unroll
            for (int j = 0; j < 8; j++)
                hp[j * 4 + tig] = __floats2half2_rn(acc[j][0], acc[j][1]);
        }
        if (ra + 8 < N_NODES) {
            __half2* hp = (__half2*)(g_hh + (size_t)(ra + 8) * HF + hd * OUT_F);
#pragma unroll
            for (int j = 0; j < 8; j++)
                hp[j * 4 + tig] = __floats2half2_rn(acc[j][2], acc[j][3]);
        }
    }
}

// ---------------- aggregation: one warp per node, ALL 8 heads ----------------
// 2-deep software pipeline: (u,m) fetched 2 ahead, aself 1 ahead.
__global__ void k_agg(float* __restrict__ out) {
    int wid = threadIdx.x >> 5, lane = threadIdx.x & 31;
    int n = blockIdx.x * 8 + wid;
    if (n >= N_NODES) return;

    int s = g_offs[n], e = g_offs[n + 1];
    const uint4* hh4 = (const uint4*)g_hh;          // 64 uint4 per node row
    const int vi = lane * 2;
    const int hsel = lane >> 2;
    const float an = __ldg(&g_aneigh[n * 8 + hsel]);

    float acc[16];
#pragma unroll
    for (int j = 0; j < 16; j++) acc[j] = 0.f;
    float den = 0.f;

    int u0 = 0, u1 = 0;
    float m0 = 0.f, m1 = 0.f, as0 = 0.f;
    if (s < e) {
        u0 = __ldg(&g_csr_src[s]); m0 = __ldg(&g_csr_m[s]);
        as0 = __ldg(&g_aself[u0 * 8 + hsel]);
    }
    if (s + 1 < e) { u1 = __ldg(&g_csr_src[s + 1]); m1 = __ldg(&g_csr_m[s + 1]); }

    for (int i = s; i < e; i++) {
        const int   uc  = u0;
        const float mc  = m0;
        const float asc = as0;
        u0 = u1; m0 = m1;
        if (i + 1 < e) as0 = __ldg(&g_aself[u0 * 8 + hsel]);
        if (i + 2 < e) { u1 = __ldg(&g_csr_src[i + 2]); m1 = __ldg(&g_csr_m[i + 2]); }

        float ev = asc + an;
        ev = (ev > 0.f) ? ev : 0.2f * ev;           // leaky_relu
        float wgt = __expf(ev * mc);
        uint4 v0 = hh4[(size_t)uc * 64 + vi];
        uint4 v1 = hh4[(size_t)uc * 64 + vi + 1];
        den += wgt;
        const __half2* p0 = (const __half2*)&v0;
        const __half2* p1 = (const __half2*)&v1;
#pragma unroll
        for (int j = 0; j < 4; j++) {
            float2 f0 = __half22float2(p0[j]);
            float2 f1 = __half22float2(p1[j]);
            acc[2*j]     = fmaf(wgt, f0.x, acc[2*j]);
            acc[2*j+1]   = fmaf(wgt, f0.y, acc[2*j+1]);
            acc[8+2*j]   = fmaf(wgt, f1.x, acc[8+2*j]);
            acc[8+2*j+1] = fmaf(wgt, f1.y, acc[8+2*j+1]);
        }
    }
    float inv = 1.f / (den + 1e-16f);
    float* op = out + (size_t)n * HF + lane * 16;
#pragma unroll
    for (int j = 0; j < 16; j++) {
        float v = acc[j] * inv;
        acc[j] = (v > 0.f) ? v : expm1f(v);         // elu
    }
#pragma unroll
    for (int j = 0; j < 4; j++)
        *(float4*)(op + j * 4) = make_float4(acc[4*j], acc[4*j+1], acc[4*j+2], acc[4*j+3]);
}

// ---------------- launch: fork CSR chain at t=0 ------------------------------
extern "C" void kernel_launch(void* const* d_in, const int* in_sizes, int n_in,
                              void* d_out, int out_size) {
    const float* x   = (const float*)d_in[0];
    const int*   src = (const int*)d_in[1];
    const int*   dst = (const int*)d_in[2];
    const float* M   = (const float*)d_in[3];
    const float* W   = (const float*)d_in[4];
    const float* a   = (const float*)d_in[5];
    float* out = (float*)d_out;

    static cudaStream_t s2 = nullptr;
    static cudaEvent_t ev_fork = nullptr, ev_join = nullptr;
    if (!s2) {
        cudaStreamCreateWithFlags(&s2, cudaStreamNonBlocking);
        cudaEventCreateWithFlags(&ev_fork, cudaEventDisableTiming);
        cudaEventCreateWithFlags(&ev_join, cudaEventDisableTiming);
        cudaFuncSetAttribute(k_gemm, cudaFuncAttributeMaxDynamicSharedMemorySize,
                             GEMM_SMEM);
    }

    // fork immediately: chain B is independent of the prep/gemm chain
    cudaEventRecord(ev_fork, 0);
    cudaStreamWaitEvent(s2, ev_fork, 0);
    k_zero_deg<<<(N_NODES + 255) / 256, 256, 0, s2>>>();                    // s2
    k_count<<<(N_EDGES + 255) / 256, 256, 0, s2>>>(dst);                    // s2
    k_scan<<<1, 1024, 0, s2>>>();                                           // s2
    k_fill<<<(N_EDGES + 255) / 256, 256, 0, s2>>>(src, dst, M);             // s2

    // chain A (stream 0): prep -> gemm
    k_prep<<<(XPAIRS + WELEMS + 255) / 256, 256>>>(x, W);
    k_gemm<<<dim3(N_HEADS, (N_NODES + BM - 1) / BM), 256, GEMM_SMEM>>>(a);

    // join, then aggregate
    cudaEventRecord(ev_join, s2);
    cudaStreamWaitEvent(0, ev_join, 0);
    k_agg<<<(N_NODES + 7) / 8, 256>>>(out);
}